// round 9
// baseline (speedup 1.0000x reference)
#include <cuda_runtime.h>
#include <cuda_bf16.h>
#include <math.h>
#include <stdint.h>

#define B_  8
#define T_  4096
#define F_  256
#define NL  8
#define M_  (B_ * T_)
#define TILE_B 16384
// 1KB header + A x2 (2x64KB) + Bh x2 (2x32KB) + Bl x1 (32KB) = 230400
#define SMEM_BYTES (1024 + 131072 + 65536 + 32768)

#if defined(__CUDA_ARCH_FEAT_SM103_ALL) || defined(__CUDA_ARCH_FEAT_SM100_ALL) || \
    defined(__CUDA_ARCH_FEAT_SM101_ALL) || defined(__CUDA_ARCH_SPECIFIC__) ||     \
    defined(__CUDA_ARCH_FAMILY_SPECIFIC__)
#define HAS_TCG 1
#else
#define HAS_TCG 0
#endif

__device__ float g_skip[M_ * F_];
__device__ float g_tmp [M_ * F_];  // fallback scratch only
__device__ __nv_bfloat16 g_outh[M_ * F_], g_outl[M_ * F_];
__device__ __nv_bfloat16 g_zh  [M_ * F_], g_zl  [M_ * F_];
// SW128 16KB tiles, per chunk ordered [hi mats..][lo mats..]
__device__ char g_gB[(size_t)NL * 2 * 8 * 4 * TILE_B];
__device__ char g_rB[(size_t)NL * 2 * 4 * 4 * TILE_B];
__device__ char g_cB[(size_t)2 * 2 * 2 * TILE_B];

__host__ __device__ __forceinline__ uint32_t swz128(uint32_t x) { return x ^ ((x >> 3) & 0x70); }
__device__ __forceinline__ float sigmoidf_(float x) { return 1.0f / (1.0f + expf(-x)); }
__device__ __forceinline__ float seluf_(float x) {
    const float sc = 1.0507009873554804934193349852946f;
    const float al = 1.6732632423543772848170429916717f;
    return x > 0.0f ? sc * x : sc * al * (expf(x) - 1.0f);
}
__device__ __forceinline__ void split2(float v, __nv_bfloat16& h, __nv_bfloat16& l) {
    h = __float2bfloat16(v);
    l = __float2bfloat16(v - __bfloat162float(h));
}
__device__ __forceinline__ uint4 pack8(const unsigned short* v) {
    return make_uint4((uint32_t)v[0] | ((uint32_t)v[1] << 16),
                      (uint32_t)v[2] | ((uint32_t)v[3] << 16),
                      (uint32_t)v[4] | ((uint32_t)v[5] << 16),
                      (uint32_t)v[6] | ((uint32_t)v[7] << 16));
}

#if HAS_TCG
__device__ __forceinline__ uint32_t elect_one_pred() {
    uint32_t p_;
    asm volatile("{\n\t.reg .pred p;\n\telect.sync _|p, 0xFFFFFFFF;\n\t"
                 "selp.b32 %0, 1, 0, p;\n\t}" : "=r"(p_));
    return p_;
}
__device__ __forceinline__ uint32_t smem_u32(const void* p) {
    uint32_t a;
    asm("{ .reg .u64 t; cvta.to.shared.u64 t, %1; cvt.u32.u64 %0, t; }" : "=r"(a) : "l"(p));
    return a;
}
#define MBARRIER_INIT(mb, c) \
    asm volatile("mbarrier.init.shared.b64 [%0], %1;" :: "r"((uint32_t)(mb)), "r"((uint32_t)(c)) : "memory")
#define MBARRIER_INVAL(mb) \
    asm volatile("mbarrier.inval.shared.b64 [%0];" :: "r"((uint32_t)(mb)) : "memory")
#define MBARRIER_EXPECT_TX(mb, bytes) \
    asm volatile("mbarrier.arrive.expect_tx.shared.b64 _, [%0], %1;" \
                 :: "r"((uint32_t)(mb)), "r"((uint32_t)(bytes)) : "memory")
#define MBARRIER_WAIT_PARITY(mb, par) do {                                              \
    uint32_t _mb = (uint32_t)(mb), _pa = (uint32_t)(par), _done;                        \
    asm volatile("{\n\t.reg .pred p;\n\t"                                               \
        "mbarrier.try_wait.parity.acquire.cta.shared::cta.b64 p, [%1], %2;\n\t"         \
        "selp.b32 %0, 1, 0, p;\n\t}" : "=r"(_done) : "r"(_mb), "r"(_pa) : "memory");    \
    if (!_done) {                                                                       \
        asm volatile("{\n\t.reg .pred P1;\n\tWL_%=:\n\t"                                \
            "mbarrier.try_wait.parity.acquire.cta.shared::cta.b64 P1, [%0], %1, 0x989680;\n\t" \
            "@P1 bra.uni WD_%=;\n\tbra.uni WL_%=;\n\tWD_%=:\n\t}"                       \
            :: "r"(_mb), "r"(_pa) : "memory");                                          \
    } } while (0)
#define CP_BULK_G2S(dst, src, bytes, mb) \
    asm volatile("cp.async.bulk.shared::cta.global.mbarrier::complete_tx::bytes " \
                 "[%0], [%1], %2, [%3];" \
                 :: "r"((uint32_t)(dst)), "l"(src), "r"((uint32_t)(bytes)), \
                    "r"((uint32_t)(mb)) : "memory")
#define TCGEN05_ALLOC(sa, nc) \
    asm volatile("tcgen05.alloc.cta_group::1.sync.aligned.shared::cta.b32 [%0], %1;" \
                 :: "r"((uint32_t)(sa)), "r"((uint32_t)(nc)) : "memory")
#define TCGEN05_DEALLOC(tm, nc) \
    asm volatile("tcgen05.dealloc.cta_group::1.sync.aligned.b32 %0, %1;" :: "r"(tm), "r"((uint32_t)(nc)))
#define TCGEN05_COMMIT(mb) \
    asm volatile("tcgen05.commit.cta_group::1.mbarrier::arrive::one.shared::cluster.b64 [%0];" \
                 :: "r"((uint32_t)(mb)) : "memory")
#define TCGEN05_WAIT_LD()     asm volatile("tcgen05.wait::ld.sync.aligned;" ::: "memory")
#define TCGEN05_FENCE_AFTER() asm volatile("tcgen05.fence::after_thread_sync;" ::: "memory")
#define FENCE_PROXY_ASYNC()   asm volatile("fence.proxy.async.shared::cta;" ::: "memory")

#define TCGEN05_LD_X32(r, ta) \
    asm volatile("tcgen05.ld.sync.aligned.32x32b.x32.b32 " \
        "{%0,%1,%2,%3,%4,%5,%6,%7,%8,%9,%10,%11,%12,%13,%14,%15," \
        "%16,%17,%18,%19,%20,%21,%22,%23,%24,%25,%26,%27,%28,%29,%30,%31}, [%32];" \
        : "=r"((r)[0]),"=r"((r)[1]),"=r"((r)[2]),"=r"((r)[3]),"=r"((r)[4]),"=r"((r)[5]), \
          "=r"((r)[6]),"=r"((r)[7]),"=r"((r)[8]),"=r"((r)[9]),"=r"((r)[10]),"=r"((r)[11]), \
          "=r"((r)[12]),"=r"((r)[13]),"=r"((r)[14]),"=r"((r)[15]),"=r"((r)[16]),"=r"((r)[17]), \
          "=r"((r)[18]),"=r"((r)[19]),"=r"((r)[20]),"=r"((r)[21]),"=r"((r)[22]),"=r"((r)[23]), \
          "=r"((r)[24]),"=r"((r)[25]),"=r"((r)[26]),"=r"((r)[27]),"=r"((r)[28]),"=r"((r)[29]), \
          "=r"((r)[30]),"=r"((r)[31]) : "r"(ta))

static __device__ __forceinline__ uint64_t make_desc(uint32_t addr) {
    const uint64_t BASE = (uint64_t(2) << 61) | (uint64_t(1) << 46) |
                          (uint64_t(64) << 32) | (uint64_t(1) << 16);
    return BASE | ((uint64_t)(addr >> 4) & 0x3FFF);
}
#define IDESC_ ((1u << 4) | (1u << 7) | (1u << 10) | (16u << 17) | (8u << 24))

__device__ __forceinline__ void mma_f16(uint32_t d, uint64_t a, uint64_t b, uint32_t en) {
    asm volatile("{\n\t.reg .pred p;\n\tsetp.ne.u32 p, %3, 0;\n\t"
        "tcgen05.mma.cta_group::1.kind::f16 [%0], %1, %2, %4, {%5,%5,%5,%5}, p;\n\t}"
        :: "r"(d), "l"(a), "l"(b), "r"(en), "r"(IDESC_), "r"(0u) : "memory");
}
#endif  // HAS_TCG

// ---------------- weight preprocessing (coalesced; tiles ordered hi..lo) ----------------
__global__ __launch_bounds__(256) void prep_gated(const float* __restrict__ Wf,
                                                  const float* __restrict__ Wg) {
    uint32_t idx = blockIdx.x * 256u + threadIdx.x;   // 2^17
    int n7 = idx & 127, kq = (idx >> 7) & 7, c = (idx >> 10) & 7;
    int nb = (idx >> 13) & 1, i = idx >> 14;
    char* base = g_gB + (((size_t)(i * 2 + nb) * 8 + c) * 4) * TILE_B;
    uint32_t off = swz128((uint32_t)n7 * 128u + (uint32_t)kq * 16u);
    unsigned short fh[8], fl[8], gh[8], gl[8];
    #pragma unroll
    for (int e = 0; e < 8; ++e) {
        int k = c * 64 + kq * 8 + e;
        size_t o = (size_t)i * 131072 + (size_t)k * 256 + nb * 128 + n7;
        __nv_bfloat16 h, l;
        split2(Wf[o], h, l); fh[e] = __bfloat16_as_ushort(h); fl[e] = __bfloat16_as_ushort(l);
        split2(Wg[o], h, l); gh[e] = __bfloat16_as_ushort(h); gl[e] = __bfloat16_as_ushort(l);
    }
    // tile order: fh, gh, fl, gl
    *(uint4*)(base + 0 * TILE_B + off) = pack8(fh);
    *(uint4*)(base + 1 * TILE_B + off) = pack8(gh);
    *(uint4*)(base + 2 * TILE_B + off) = pack8(fl);
    *(uint4*)(base + 3 * TILE_B + off) = pack8(gl);
}
__global__ __launch_bounds__(256) void prep_res(const float* __restrict__ Wr,
                                                const float* __restrict__ Ws) {
    uint32_t idx = blockIdx.x * 256u + threadIdx.x;   // 2^16
    int n7 = idx & 127, kq = (idx >> 7) & 7, c = (idx >> 10) & 3;
    int nb = (idx >> 12) & 1, i = idx >> 13;
    char* base = g_rB + (((size_t)(i * 2 + nb) * 4 + c) * 4) * TILE_B;
    uint32_t off = swz128((uint32_t)n7 * 128u + (uint32_t)kq * 16u);
    unsigned short rh[8], rl[8], sh[8], sl[8];
    #pragma unroll
    for (int e = 0; e < 8; ++e) {
        int k = c * 64 + kq * 8 + e;
        size_t o = (size_t)i * 65536 + (size_t)k * 256 + nb * 128 + n7;
        __nv_bfloat16 h, l;
        split2(Wr[o], h, l); rh[e] = __bfloat16_as_ushort(h); rl[e] = __bfloat16_as_ushort(l);
        split2(Ws[o], h, l); sh[e] = __bfloat16_as_ushort(h); sl[e] = __bfloat16_as_ushort(l);
    }
    // tile order: rh, sh, rl, sl
    *(uint4*)(base + 0 * TILE_B + off) = pack8(rh);
    *(uint4*)(base + 1 * TILE_B + off) = pack8(sh);
    *(uint4*)(base + 2 * TILE_B + off) = pack8(rl);
    *(uint4*)(base + 3 * TILE_B + off) = pack8(sl);
}
__global__ __launch_bounds__(256) void prep_conv(const float* __restrict__ Wc) {
    uint32_t idx = blockIdx.x * 256u + threadIdx.x;   // 4096
    int n7 = idx & 127, kq = (idx >> 7) & 7, c = (idx >> 10) & 1, nb = (idx >> 11) & 1;
    char* base = g_cB + (((size_t)nb * 2 + c) * 2) * TILE_B;
    uint32_t off = swz128((uint32_t)n7 * 128u + (uint32_t)kq * 16u);
    unsigned short hv[8], lv[8];
    #pragma unroll
    for (int e = 0; e < 8; ++e) {
        int k = c * 64 + kq * 8 + e;
        size_t o = (size_t)k * 256 + nb * 128 + n7;
        __nv_bfloat16 h, l;
        split2(Wc[o], h, l); hv[e] = __bfloat16_as_ushort(h); lv[e] = __bfloat16_as_ushort(l);
    }
    *(uint4*)(base + 0 * TILE_B + off) = pack8(hv);
    *(uint4*)(base + 1 * TILE_B + off) = pack8(lv);
}

// ---------------- A-tile fills (per 128-row subtile, SW128) ----------------
__device__ __forceinline__ void fill_A_f32(char* Ah, char* Al, const float* Asrc,
                                           int b, int srow, int fr, int cg,
                                           int c, int shift_chunks, int dil) {
    const int tsh  = (c < shift_chunks) ? dil : 0;
    const int kcol = (c < shift_chunks) ? c * 64 : (c - shift_chunks) * 64;
    const int t = srow - tsh;
    const bool valid = srow >= tsh;
    const float* src = Asrc + ((size_t)(b * T_ + t)) * 64 + kcol + cg;
    #pragma unroll
    for (int j = 0; j < 8; ++j) {
        float4 v = valid ? *(const float4*)(src + j * 4) : make_float4(0.f, 0.f, 0.f, 0.f);
        uint32_t off = swz128((uint32_t)fr * 128u + (uint32_t)(cg + j * 4) * 2u);
        __nv_bfloat16 h0, l0, h1, l1, h2, l2, h3, l3;
        split2(v.x, h0, l0); split2(v.y, h1, l1);
        split2(v.z, h2, l2); split2(v.w, h3, l3);
        uint2 hh, ll;
        hh.x = (uint32_t)__bfloat16_as_ushort(h0) | ((uint32_t)__bfloat16_as_ushort(h1) << 16);
        hh.y = (uint32_t)__bfloat16_as_ushort(h2) | ((uint32_t)__bfloat16_as_ushort(h3) << 16);
        ll.x = (uint32_t)__bfloat16_as_ushort(l0) | ((uint32_t)__bfloat16_as_ushort(l1) << 16);
        ll.y = (uint32_t)__bfloat16_as_ushort(l2) | ((uint32_t)__bfloat16_as_ushort(l3) << 16);
        *(uint2*)(Ah + off) = hh;
        *(uint2*)(Al + off) = ll;
    }
}
__device__ __forceinline__ void fill_A_bf16(char* Ah, char* Al,
                                            const __nv_bfloat16* __restrict__ sh,
                                            const __nv_bfloat16* __restrict__ sl,
                                            int b, int srow, int fr, int cg,
                                            int c, int shift_chunks, int dil) {
    const int tsh  = (c < shift_chunks) ? dil : 0;
    const int kcol = (c < shift_chunks) ? c * 64 : (c - shift_chunks) * 64;
    const int t = srow - tsh;
    const bool valid = srow >= tsh;
    const size_t eoff = ((size_t)(b * T_ + t)) * F_ + kcol + cg;
    const uint4* ph = (const uint4*)(sh + eoff);
    const uint4* pl = (const uint4*)(sl + eoff);
    #pragma unroll
    for (int j = 0; j < 4; ++j) {
        uint4 vh = valid ? ph[j] : make_uint4(0, 0, 0, 0);
        uint4 vl = valid ? pl[j] : make_uint4(0, 0, 0, 0);
        uint32_t off = swz128((uint32_t)fr * 128u + (uint32_t)(cg + j * 8) * 2u);
        *(uint4*)(Ah + off) = vh;
        *(uint4*)(Al + off) = vl;
    }
}

__device__ __forceinline__ void store_hl8(__nv_bfloat16* hd, __nv_bfloat16* ld,
                                          size_t eoff, const float* v) {
    unsigned short hu[8], lu[8];
    #pragma unroll
    for (int e = 0; e < 8; ++e) {
        __nv_bfloat16 h, l; split2(v[e], h, l);
        hu[e] = __bfloat16_as_ushort(h); lu[e] = __bfloat16_as_ushort(l);
    }
    *(uint4*)(hd + eoff) = pack8(hu);
    *(uint4*)(ld + eoff) = pack8(lu);
}
__device__ __forceinline__ void load_hl8(const __nv_bfloat16* hd, const __nv_bfloat16* ld,
                                         size_t eoff, float* v) {
    uint4 hh = *(const uint4*)(hd + eoff);
    uint4 ll = *(const uint4*)(ld + eoff);
    const uint32_t* hp = &hh.x;
    const uint32_t* lp = &ll.x;
    #pragma unroll
    for (int e = 0; e < 4; ++e) {
        __nv_bfloat162 h2 = *(__nv_bfloat162*)&hp[e];
        __nv_bfloat162 l2 = *(__nv_bfloat162*)&lp[e];
        float2 fh = __bfloat1622float2(h2), fl = __bfloat1622float2(l2);
        v[2 * e] = fh.x + fl.x;
        v[2 * e + 1] = fh.y + fl.y;
    }
}
__device__ __forceinline__ float2 dec2(const char* hp, const char* lp, uint32_t off) {
    __nv_bfloat162 h = *(const __nv_bfloat162*)(hp + off);
    __nv_bfloat162 l = *(const __nv_bfloat162*)(lp + off);
    float2 fh = __bfloat1622float2(h), fl = __bfloat1622float2(l);
    return make_float2(fh.x + fl.x, fh.y + fl.y);
}

// ---------------- unified GEMM layer: M=256/CTA, A x2 + Bh x2 + Bl x1 ----------------
// mode 0: conv0 (fp32 A) -> outh/l; 1: gated -> zh/zl; 2: res/skip RMW (hi/lo residual)
__global__ __launch_bounds__(256, 1) void mma_layer(
    const float* __restrict__ Af32,
    const __nv_bfloat16* __restrict__ Abh, const __nv_bfloat16* __restrict__ Abl,
    const char* __restrict__ Bbase,
    const float* __restrict__ br, const float* __restrict__ bs,
    int n_chunks, int n_mats, int shift_chunks, int dil, int mode, int first)
{
    extern __shared__ char smem[];
    const int tid = threadIdx.x;
    const int m0 = blockIdx.x * 256;
    const int n0 = blockIdx.y * 128;
    const int b  = m0 / T_;
    const int t0 = m0 % T_;
    const uint32_t half_bytes = (uint32_t)n_mats * TILE_B;   // Bh or Bl bytes per chunk
    const int fr = tid >> 1;
    const int cg = (tid & 1) * 32;

#if HAS_TCG
    const uint32_t sbase = smem_u32(smem);
    const int wid = tid >> 5;
    const uint32_t mC0 = sbase, mC1 = sbase + 8;         // per-chunk commit (alternating)
    const uint32_t bh0 = sbase + 16, bh1 = sbase + 24;   // Bh copy barriers
    const uint32_t blb = sbase + 32;                     // Bl copy barrier (single)
    const uint32_t tptr = sbase + 48;
    const uint32_t abase0 = sbase + 1024;                // A bufs 2 x 64KB
    const uint32_t bhsm0  = abase0 + 131072;             // Bh bufs 2 x 32KB
    const uint32_t blsm   = bhsm0 + 65536;               // Bl buf 32KB

    if (tid == 0) {
        MBARRIER_INIT(mC0, 1); MBARRIER_INIT(mC1, 1);
        MBARRIER_INIT(bh0, 1); MBARRIER_INIT(bh1, 1);
        MBARRIER_INIT(blb, 1);
    }
    if (wid == 0) TCGEN05_ALLOC(tptr, 512);
    __syncthreads();
    uint32_t tmem;
    asm volatile("ld.shared.b32 %0, [%1];" : "=r"(tmem) : "r"(tptr));

    // prologue: Bh(0), Bl(0)
    if (tid == 0) {
        const char* cb = Bbase + ((size_t)(blockIdx.y * n_chunks + 0) * 2 * n_mats) * TILE_B;
        MBARRIER_EXPECT_TX(bh0, half_bytes);
        CP_BULK_G2S(bhsm0, cb, half_bytes, bh0);
        MBARRIER_EXPECT_TX(blb, half_bytes);
        CP_BULK_G2S(blsm, cb + half_bytes, half_bytes, blb);
    }

    for (int c = 0; c < n_chunks; ++c) {
        const int buf = c & 1;
        const uint32_t abase = abase0 + buf * 65536u;
        char* Abuf = smem + 1024 + buf * 65536;

        // A buf reused from chunk c-2: wait its MMA chain complete
        if (c >= 2) MBARRIER_WAIT_PARITY(buf ? mC1 : mC0, ((c - 2) >> 1) & 1);

        if (mode == 0) {
            fill_A_f32(Abuf,         Abuf + TILE_B,
                       Af32, b, t0 + fr, fr, cg, c, shift_chunks, dil);
            fill_A_f32(Abuf + 32768, Abuf + 32768 + TILE_B,
                       Af32, b, t0 + 128 + fr, fr, cg, c, shift_chunks, dil);
        } else {
            fill_A_bf16(Abuf,         Abuf + TILE_B,
                        Abh, Abl, b, t0 + fr, fr, cg, c, shift_chunks, dil);
            fill_A_bf16(Abuf + 32768, Abuf + 32768 + TILE_B,
                        Abh, Abl, b, t0 + 128 + fr, fr, cg, c, shift_chunks, dil);
        }
        FENCE_PROXY_ASYNC();
        __syncthreads();

        if (wid == 0) {
            // 1) Bh(c) ready
            MBARRIER_WAIT_PARITY(buf ? bh1 : bh0, (c >> 1) & 1);
            const uint32_t one = elect_one_pred();
            const uint32_t bhsm = bhsm0 + buf * 32768u;
            if (one) {
                // 2) issue Bh-dependent MMAs: AhBh + AlBh
                #pragma unroll
                for (int s = 0; s < 2; ++s) {
                    const uint64_t ah = make_desc(abase + s * 32768u);
                    const uint64_t al = make_desc(abase + s * 32768u + TILE_B);
                    for (int mat = 0; mat < n_mats; ++mat) {
                        const uint64_t bh = make_desc(bhsm + (uint32_t)mat * TILE_B);
                        const uint32_t dD = tmem + s * 256 + mat * 128;
                        #pragma unroll
                        for (int ks = 0; ks < 4; ++ks)
                            mma_f16(dD, ah + ks * 2, bh + ks * 2, !(c == 0 && ks == 0));
                        #pragma unroll
                        for (int ks = 0; ks < 4; ++ks)
                            mma_f16(dD, al + ks * 2, bh + ks * 2, 1u);
                    }
                }
            }
            // 3) chunk c-1 fully done -> Bh buf(c+1) and Bl buf free
            if (c >= 1)
                MBARRIER_WAIT_PARITY((c - 1) & 1 ? mC1 : mC0, ((c - 1) >> 1) & 1);
            if (one) {
                // 4) prefetch Bh(c+1)
                if (c + 1 < n_chunks) {
                    const uint32_t nb_ = (c + 1) & 1;
                    const char* cb = Bbase +
                        ((size_t)(blockIdx.y * n_chunks + c + 1) * 2 * n_mats) * TILE_B;
                    MBARRIER_EXPECT_TX(nb_ ? bh1 : bh0, half_bytes);
                    CP_BULK_G2S(bhsm0 + nb_ * 32768u, cb, half_bytes, nb_ ? bh1 : bh0);
                }
                // 5) copy Bl(c) (c=0 done in prologue)
                if (c >= 1) {
                    const char* cb = Bbase +
                        ((size_t)(blockIdx.y * n_chunks + c) * 2 * n_mats) * TILE_B;
                    MBARRIER_EXPECT_TX(blb, half_bytes);
                    CP_BULK_G2S(blsm, cb + half_bytes, half_bytes, blb);
                }
            }
            // 6) Bl(c) ready
            MBARRIER_WAIT_PARITY(blb, c & 1);
            if (one) {
                // 7) issue AhBl MMAs
                #pragma unroll
                for (int s = 0; s < 2; ++s) {
                    const uint64_t ah = make_desc(abase + s * 32768u);
                    for (int mat = 0; mat < n_mats; ++mat) {
                        const uint64_t bl = make_desc(blsm + (uint32_t)mat * TILE_B);
                        const uint32_t dD = tmem + s * 256 + mat * 128;
                        #pragma unroll
                        for (int ks = 0; ks < 4; ++ks)
                            mma_f16(dD, ah + ks * 2, bl + ks * 2, 1u);
                    }
                }
                // 8) commit chunk c
                TCGEN05_COMMIT(buf ? mC1 : mC0);
            }
        }
    }

    MBARRIER_WAIT_PARITY((n_chunks - 1) & 1 ? mC1 : mC0, ((n_chunks - 1) >> 1) & 1);
    TCGEN05_FENCE_AFTER();

    // epilogue: all 8 warps (wid>>2 = subtile)
    {
        const int lane = tid & 31;
        const int sub = wid >> 2;
        const int m = m0 + sub * 128 + (wid & 3) * 32 + lane;
        const uint32_t tb = tmem + sub * 256;
        #pragma unroll
        for (int cb = 0; cb < 4; ++cb) {
            uint32_t rf[32], rg[32];
            TCGEN05_LD_X32(rf, tb + cb * 32);
            if (n_mats == 2) TCGEN05_LD_X32(rg, tb + 128 + cb * 32);
            TCGEN05_WAIT_LD();
            const int nc = n0 + cb * 32;
            const size_t rbase = (size_t)m * F_ + nc;
            if (mode == 1) {
                #pragma unroll
                for (int jq = 0; jq < 4; ++jq) {
                    float vv[8];
                    #pragma unroll
                    for (int e = 0; e < 8; ++e)
                        vv[e] = tanhf(__uint_as_float(rf[jq * 8 + e])) *
                                sigmoidf_(__uint_as_float(rg[jq * 8 + e]));
                    store_hl8(g_zh, g_zl, rbase + jq * 8, vv);
                }
            } else if (mode == 0) {
                #pragma unroll
                for (int jq = 0; jq < 4; ++jq) {
                    float vv[8];
                    #pragma unroll
                    for (int e = 0; e < 8; ++e) vv[e] = __uint_as_float(rf[jq * 8 + e]);
                    store_hl8(g_outh, g_outl, rbase + jq * 8, vv);
                }
            } else {
                #pragma unroll
                for (int jq = 0; jq < 4; ++jq) {
                    float vv[8];
                    load_hl8(g_outh, g_outl, rbase + jq * 8, vv);
                    #pragma unroll
                    for (int e = 0; e < 8; ++e) {
                        const size_t off = rbase + jq * 8 + e;
                        const int n = nc + jq * 8 + e;
                        vv[e] += __uint_as_float(rf[jq * 8 + e]) + __ldg(&br[n]);
                        const float sp = first ? 0.0f : g_skip[off];
                        g_skip[off] = sp + __uint_as_float(rg[jq * 8 + e]) + __ldg(&bs[n]);
                    }
                    store_hl8(g_outh, g_outl, rbase + jq * 8, vv);
                }
            }
        }
    }
    __syncthreads();
    if (tid == 0) {
        MBARRIER_INVAL(mC0); MBARRIER_INVAL(mC1);
        MBARRIER_INVAL(bh0); MBARRIER_INVAL(bh1); MBARRIER_INVAL(blb);
    }
    if (wid == 0) TCGEN05_DEALLOC(tmem, 512);
#else
    // ---- generic-arch fallback (compile-only; runtime uses sm_103a cubin) ----
    char* Abuf = smem;               // 64KB (2 subtiles hi/lo)
    char* Bt   = smem + 65536;       // 32KB (one mat hi+lo)
    const int ty = tid >> 4, tx = tid & 15;

    for (int sub = 0; sub < 2; ++sub) {
        for (int mat = 0; mat < n_mats; ++mat) {
            float acc[8][8];
            #pragma unroll
            for (int i = 0; i < 8; ++i)
                #pragma unroll
                for (int j = 0; j < 8; ++j) acc[i][j] = 0.0f;
            for (int c = 0; c < n_chunks; ++c) {
                __syncthreads();
                char* Ah = Abuf + sub * 32768;
                if (mode == 0)
                    fill_A_f32(Ah, Ah + TILE_B, Af32, b, t0 + sub * 128 + fr, fr, cg, c, shift_chunks, dil);
                else
                    fill_A_bf16(Ah, Ah + TILE_B, Abh, Abl, b, t0 + sub * 128 + fr, fr, cg, c, shift_chunks, dil);
                {
                    const char* cb = Bbase + ((size_t)(blockIdx.y * n_chunks + c) * 2 * n_mats) * TILE_B;
                    const uint4* srcH = (const uint4*)(cb + (size_t)mat * TILE_B);
                    const uint4* srcL = (const uint4*)(cb + (size_t)(n_mats + mat) * TILE_B);
                    uint4* dst = (uint4*)Bt;
                    for (int j = tid; j < 1024; j += 256) { dst[j] = srcH[j]; dst[j + 1024] = srcL[j]; }
                }
                __syncthreads();
                #pragma unroll 4
                for (int k2 = 0; k2 < 32; ++k2) {
                    float2 a2[8], b2[8];
                    #pragma unroll
                    for (int i = 0; i < 8; ++i)
                        a2[i] = dec2(Ah, Ah + TILE_B, swz128((uint32_t)(ty * 8 + i) * 128u + k2 * 4u));
                    #pragma unroll
                    for (int j = 0; j < 8; ++j)
                        b2[j] = dec2(Bt, Bt + TILE_B, swz128((uint32_t)(tx * 8 + j) * 128u + k2 * 4u));
                    #pragma unroll
                    for (int i = 0; i < 8; ++i)
                        #pragma unroll
                        for (int j = 0; j < 8; ++j)
                            acc[i][j] += a2[i].x * b2[j].x + a2[i].y * b2[j].y;
                }
            }
            #pragma unroll
            for (int i = 0; i < 8; ++i) {
                const int m = m0 + sub * 128 + ty * 8 + i;
                #pragma unroll
                for (int j = 0; j < 8; ++j) {
                    const int n = n0 + tx * 8 + j;
                    const size_t off = (size_t)m * F_ + n;
                    if (mode == 0) {
                        __nv_bfloat16 h, l; split2(acc[i][j], h, l);
                        g_outh[off] = h; g_outl[off] = l;
                    } else if (mode == 1) {
                        if (mat == 0) g_tmp[off] = acc[i][j];
                        else {
                            float z = tanhf(g_tmp[off]) * sigmoidf_(acc[i][j]);
                            __nv_bfloat16 h, l; split2(z, h, l);
                            g_zh[off] = h; g_zl[off] = l;
                        }
                    } else {
                        if (mat == 0) {
                            float v = __bfloat162float(g_outh[off]) +
                                      __bfloat162float(g_outl[off]) + acc[i][j] + br[n];
                            __nv_bfloat16 h, l; split2(v, h, l);
                            g_outh[off] = h; g_outl[off] = l;
                        } else {
                            const float sp = first ? 0.0f : g_skip[off];
                            g_skip[off] = sp + acc[i][j] + bs[n];
                        }
                    }
                }
            }
        }
    }
#endif
}

// ---------------- head: 32 rows/block, 8 outputs/thread ----------------
__global__ __launch_bounds__(256) void head_kernel(
    const float* __restrict__ Wd1, const float* __restrict__ bd1,
    const float* __restrict__ Wd2, const float* __restrict__ bd2,
    float* __restrict__ y) {
    __shared__ float hs[32][260];
    __shared__ float h2s[32][68];
    const int m0 = blockIdx.x * 32;
    const int r  = threadIdx.x >> 3;
    const int cg = (threadIdx.x & 7) * 8;

    for (int idx = threadIdx.x; idx < 32 * 64; idx += 256) {
        const int row = idx >> 6;
        const int c4  = (idx & 63) * 4;
        float4 v = *(const float4*)&g_skip[(size_t)(m0 + row) * F_ + c4];
        hs[row][c4 + 0] = seluf_(v.x); hs[row][c4 + 1] = seluf_(v.y);
        hs[row][c4 + 2] = seluf_(v.z); hs[row][c4 + 3] = seluf_(v.w);
    }
    __syncthreads();

    float acc[8];
    #pragma unroll
    for (int e = 0; e < 8; ++e) acc[e] = bd1[cg + e];
    #pragma unroll 4
    for (int k = 0; k < 256; ++k) {
        const float h = hs[r][k];
        float4 w0 = __ldg((const float4*)&Wd1[(size_t)k * 64 + cg]);
        float4 w1 = __ldg((const float4*)&Wd1[(size_t)k * 64 + cg + 4]);
        acc[0] += h * w0.x; acc[1] += h * w0.y; acc[2] += h * w0.z; acc[3] += h * w0.w;
        acc[4] += h * w1.x; acc[5] += h * w1.y; acc[6] += h * w1.z; acc[7] += h * w1.w;
    }
    #pragma unroll
    for (int e = 0; e < 8; ++e) h2s[r][cg + e] = seluf_(acc[e]);
    __syncthreads();

    float a2[8];
    #pragma unroll
    for (int e = 0; e < 8; ++e) a2[e] = bd2[cg + e];
    #pragma unroll 4
    for (int k = 0; k < 64; ++k) {
        const float h = h2s[r][k];
        float4 w0 = __ldg((const float4*)&Wd2[(size_t)k * 64 + cg]);
        float4 w1 = __ldg((const float4*)&Wd2[(size_t)k * 64 + cg + 4]);
        a2[0] += h * w0.x; a2[1] += h * w0.y; a2[2] += h * w0.z; a2[3] += h * w0.w;
        a2[4] += h * w1.x; a2[5] += h * w1.y; a2[6] += h * w1.z; a2[7] += h * w1.w;
    }
    float* yp = &y[(size_t)(m0 + r) * 64 + cg];
    *(float4*)yp       = make_float4(a2[0], a2[1], a2[2], a2[3]);
    *(float4*)(yp + 4) = make_float4(a2[4], a2[5], a2[6], a2[7]);
}

// ---------------------------------------------------------------------------
extern "C" void kernel_launch(void* const* d_in, const int* in_sizes, int n_in,
                              void* d_out, int out_size) {
    const float* x   = (const float*)d_in[0];
    const float* Wc  = (const float*)d_in[1];
    const float* Wf  = (const float*)d_in[2];
    const float* Wg  = (const float*)d_in[3];
    const float* Wr  = (const float*)d_in[4];
    const float* br  = (const float*)d_in[5];
    const float* Ws  = (const float*)d_in[6];
    const float* bs  = (const float*)d_in[7];
    const float* Wd1 = (const float*)d_in[8];
    const float* bd1 = (const float*)d_in[9];
    const float* Wd2 = (const float*)d_in[10];
    const float* bd2 = (const float*)d_in[11];
    float* y = (float*)d_out;

    cudaFuncSetAttribute(mma_layer, cudaFuncAttributeMaxDynamicSharedMemorySize, SMEM_BYTES);

    char* gB; cudaGetSymbolAddress((void**)&gB, g_gB);
    char* rB; cudaGetSymbolAddress((void**)&rB, g_rB);
    char* cB; cudaGetSymbolAddress((void**)&cB, g_cB);
    __nv_bfloat16 *oh, *ol, *zh, *zl;
    cudaGetSymbolAddress((void**)&oh, g_outh);
    cudaGetSymbolAddress((void**)&ol, g_outl);
    cudaGetSymbolAddress((void**)&zh, g_zh);
    cudaGetSymbolAddress((void**)&zl, g_zl);

    prep_gated<<<512, 256>>>(Wf, Wg);
    prep_res  <<<256, 256>>>(Wr, Ws);
    prep_conv <<<16,  256>>>(Wc);

    dim3 grid(M_ / 256, 2), blk(256);
    mma_layer<<<grid, blk, SMEM_BYTES>>>(x, nullptr, nullptr, cB, nullptr, nullptr,
                                         2, 1, 1, 1, 0, 0);
    for (int i = 0; i < NL; ++i) {
        const int d = 2 << i;
        mma_layer<<<grid, blk, SMEM_BYTES>>>(
            nullptr, oh, ol, gB + (size_t)i * 2 * 8 * 4 * TILE_B, nullptr, nullptr,
            8, 2, 4, d, 1, 0);
        mma_layer<<<grid, blk, SMEM_BYTES>>>(
            nullptr, zh, zl, rB + (size_t)i * 2 * 4 * 4 * TILE_B,
            br + (size_t)i * F_, bs + (size_t)i * F_,
            4, 2, 0, 0, 2, i == 0);
    }
    head_kernel<<<M_ / 32, 256>>>(Wd1, bd1, Wd2, bd2, y);
}

// round 10
// speedup vs baseline: 1.0759x; 1.0759x over previous
#include <cuda_runtime.h>
#include <cuda_bf16.h>
#include <math.h>
#include <stdint.h>

#define B_  8
#define T_  4096
#define F_  256
#define NL  8
#define M_  (B_ * T_)
#define TILE_B 16384
// 1KB header + A single (32KB) + B single (64KB) = 97KB -> 2 CTAs/SM
#define SMEM_BYTES (1024 + 32768 + 65536)

#if defined(__CUDA_ARCH_FEAT_SM103_ALL) || defined(__CUDA_ARCH_FEAT_SM100_ALL) || \
    defined(__CUDA_ARCH_FEAT_SM101_ALL) || defined(__CUDA_ARCH_SPECIFIC__) ||     \
    defined(__CUDA_ARCH_FAMILY_SPECIFIC__)
#define HAS_TCG 1
#else
#define HAS_TCG 0
#endif

__device__ float g_skip[M_ * F_];
__device__ float g_tmp [M_ * F_];  // fallback scratch only
__device__ __nv_bfloat16 g_outh[M_ * F_], g_outl[M_ * F_];
__device__ __nv_bfloat16 g_zh  [M_ * F_], g_zl  [M_ * F_];
// SW128 16KB tiles: per chunk [fh, fl, gh, gl]
__device__ char g_gB[(size_t)NL * 2 * 8 * 4 * TILE_B];
__device__ char g_rB[(size_t)NL * 2 * 4 * 4 * TILE_B];
__device__ char g_cB[(size_t)2 * 2 * 2 * TILE_B];

__host__ __device__ __forceinline__ uint32_t swz128(uint32_t x) { return x ^ ((x >> 3) & 0x70); }
__device__ __forceinline__ float sigmoidf_(float x) { return 1.0f / (1.0f + expf(-x)); }
__device__ __forceinline__ float seluf_(float x) {
    const float sc = 1.0507009873554804934193349852946f;
    const float al = 1.6732632423543772848170429916717f;
    return x > 0.0f ? sc * x : sc * al * (expf(x) - 1.0f);
}
__device__ __forceinline__ void split2(float v, __nv_bfloat16& h, __nv_bfloat16& l) {
    h = __float2bfloat16(v);
    l = __float2bfloat16(v - __bfloat162float(h));
}
__device__ __forceinline__ uint4 pack8(const unsigned short* v) {
    return make_uint4((uint32_t)v[0] | ((uint32_t)v[1] << 16),
                      (uint32_t)v[2] | ((uint32_t)v[3] << 16),
                      (uint32_t)v[4] | ((uint32_t)v[5] << 16),
                      (uint32_t)v[6] | ((uint32_t)v[7] << 16));
}

#if HAS_TCG
__device__ __forceinline__ uint32_t elect_one_pred() {
    uint32_t p_;
    asm volatile("{\n\t.reg .pred p;\n\telect.sync _|p, 0xFFFFFFFF;\n\t"
                 "selp.b32 %0, 1, 0, p;\n\t}" : "=r"(p_));
    return p_;
}
__device__ __forceinline__ uint32_t smem_u32(const void* p) {
    uint32_t a;
    asm("{ .reg .u64 t; cvta.to.shared.u64 t, %1; cvt.u32.u64 %0, t; }" : "=r"(a) : "l"(p));
    return a;
}
#define MBARRIER_INIT(mb, c) \
    asm volatile("mbarrier.init.shared.b64 [%0], %1;" :: "r"((uint32_t)(mb)), "r"((uint32_t)(c)) : "memory")
#define MBARRIER_INVAL(mb) \
    asm volatile("mbarrier.inval.shared.b64 [%0];" :: "r"((uint32_t)(mb)) : "memory")
#define MBARRIER_EXPECT_TX(mb, bytes) \
    asm volatile("mbarrier.arrive.expect_tx.shared.b64 _, [%0], %1;" \
                 :: "r"((uint32_t)(mb)), "r"((uint32_t)(bytes)) : "memory")
#define MBARRIER_WAIT_PARITY(mb, par) do {                                              \
    uint32_t _mb = (uint32_t)(mb), _pa = (uint32_t)(par), _done;                        \
    asm volatile("{\n\t.reg .pred p;\n\t"                                               \
        "mbarrier.try_wait.parity.acquire.cta.shared::cta.b64 p, [%1], %2;\n\t"         \
        "selp.b32 %0, 1, 0, p;\n\t}" : "=r"(_done) : "r"(_mb), "r"(_pa) : "memory");    \
    if (!_done) {                                                                       \
        asm volatile("{\n\t.reg .pred P1;\n\tWL_%=:\n\t"                                \
            "mbarrier.try_wait.parity.acquire.cta.shared::cta.b64 P1, [%0], %1, 0x989680;\n\t" \
            "@P1 bra.uni WD_%=;\n\tbra.uni WL_%=;\n\tWD_%=:\n\t}"                       \
            :: "r"(_mb), "r"(_pa) : "memory");                                          \
    } } while (0)
#define CP_BULK_G2S(dst, src, bytes, mb) \
    asm volatile("cp.async.bulk.shared::cta.global.mbarrier::complete_tx::bytes " \
                 "[%0], [%1], %2, [%3];" \
                 :: "r"((uint32_t)(dst)), "l"(src), "r"((uint32_t)(bytes)), \
                    "r"((uint32_t)(mb)) : "memory")
#define TCGEN05_ALLOC(sa, nc) \
    asm volatile("tcgen05.alloc.cta_group::1.sync.aligned.shared::cta.b32 [%0], %1;" \
                 :: "r"((uint32_t)(sa)), "r"((uint32_t)(nc)) : "memory")
#define TCGEN05_DEALLOC(tm, nc) \
    asm volatile("tcgen05.dealloc.cta_group::1.sync.aligned.b32 %0, %1;" :: "r"(tm), "r"((uint32_t)(nc)))
#define TCGEN05_COMMIT(mb) \
    asm volatile("tcgen05.commit.cta_group::1.mbarrier::arrive::one.shared::cluster.b64 [%0];" \
                 :: "r"((uint32_t)(mb)) : "memory")
#define TCGEN05_WAIT_LD()     asm volatile("tcgen05.wait::ld.sync.aligned;" ::: "memory")
#define TCGEN05_FENCE_AFTER() asm volatile("tcgen05.fence::after_thread_sync;" ::: "memory")
#define FENCE_PROXY_ASYNC()   asm volatile("fence.proxy.async.shared::cta;" ::: "memory")

#define TCGEN05_LD_X16(r, ta) \
    asm volatile("tcgen05.ld.sync.aligned.32x32b.x16.b32 " \
        "{%0,%1,%2,%3,%4,%5,%6,%7,%8,%9,%10,%11,%12,%13,%14,%15}, [%16];" \
        : "=r"((r)[0]),"=r"((r)[1]),"=r"((r)[2]),"=r"((r)[3]), \
          "=r"((r)[4]),"=r"((r)[5]),"=r"((r)[6]),"=r"((r)[7]), \
          "=r"((r)[8]),"=r"((r)[9]),"=r"((r)[10]),"=r"((r)[11]), \
          "=r"((r)[12]),"=r"((r)[13]),"=r"((r)[14]),"=r"((r)[15]) : "r"(ta))

static __device__ __forceinline__ uint64_t make_desc(uint32_t addr) {
    const uint64_t BASE = (uint64_t(2) << 61) | (uint64_t(1) << 46) |
                          (uint64_t(64) << 32) | (uint64_t(1) << 16);
    return BASE | ((uint64_t)(addr >> 4) & 0x3FFF);
}
#define IDESC_ ((1u << 4) | (1u << 7) | (1u << 10) | (16u << 17) | (8u << 24))

__device__ __forceinline__ void mma_f16(uint32_t d, uint64_t a, uint64_t b, uint32_t en) {
    asm volatile("{\n\t.reg .pred p;\n\tsetp.ne.u32 p, %3, 0;\n\t"
        "tcgen05.mma.cta_group::1.kind::f16 [%0], %1, %2, %4, {%5,%5,%5,%5}, p;\n\t}"
        :: "r"(d), "l"(a), "l"(b), "r"(en), "r"(IDESC_), "r"(0u) : "memory");
}
#endif  // HAS_TCG

// ---------------- weight preprocessing (coalesced 16B writes) ----------------
__global__ __launch_bounds__(256) void prep_gated(const float* __restrict__ Wf,
                                                  const float* __restrict__ Wg) {
    uint32_t idx = blockIdx.x * 256u + threadIdx.x;   // 2^17
    int n7 = idx & 127, kq = (idx >> 7) & 7, c = (idx >> 10) & 7;
    int nb = (idx >> 13) & 1, i = idx >> 14;
    char* base = g_gB + (((size_t)(i * 2 + nb) * 8 + c) * 4) * TILE_B;
    uint32_t off = swz128((uint32_t)n7 * 128u + (uint32_t)kq * 16u);
    unsigned short fh[8], fl[8], gh[8], gl[8];
    #pragma unroll
    for (int e = 0; e < 8; ++e) {
        int k = c * 64 + kq * 8 + e;
        size_t o = (size_t)i * 131072 + (size_t)k * 256 + nb * 128 + n7;
        __nv_bfloat16 h, l;
        split2(Wf[o], h, l); fh[e] = __bfloat16_as_ushort(h); fl[e] = __bfloat16_as_ushort(l);
        split2(Wg[o], h, l); gh[e] = __bfloat16_as_ushort(h); gl[e] = __bfloat16_as_ushort(l);
    }
    *(uint4*)(base + 0 * TILE_B + off) = pack8(fh);
    *(uint4*)(base + 1 * TILE_B + off) = pack8(fl);
    *(uint4*)(base + 2 * TILE_B + off) = pack8(gh);
    *(uint4*)(base + 3 * TILE_B + off) = pack8(gl);
}
__global__ __launch_bounds__(256) void prep_res(const float* __restrict__ Wr,
                                                const float* __restrict__ Ws) {
    uint32_t idx = blockIdx.x * 256u + threadIdx.x;   // 2^16
    int n7 = idx & 127, kq = (idx >> 7) & 7, c = (idx >> 10) & 3;
    int nb = (idx >> 12) & 1, i = idx >> 13;
    char* base = g_rB + (((size_t)(i * 2 + nb) * 4 + c) * 4) * TILE_B;
    uint32_t off = swz128((uint32_t)n7 * 128u + (uint32_t)kq * 16u);
    unsigned short rh[8], rl[8], sh[8], sl[8];
    #pragma unroll
    for (int e = 0; e < 8; ++e) {
        int k = c * 64 + kq * 8 + e;
        size_t o = (size_t)i * 65536 + (size_t)k * 256 + nb * 128 + n7;
        __nv_bfloat16 h, l;
        split2(Wr[o], h, l); rh[e] = __bfloat16_as_ushort(h); rl[e] = __bfloat16_as_ushort(l);
        split2(Ws[o], h, l); sh[e] = __bfloat16_as_ushort(h); sl[e] = __bfloat16_as_ushort(l);
    }
    *(uint4*)(base + 0 * TILE_B + off) = pack8(rh);
    *(uint4*)(base + 1 * TILE_B + off) = pack8(rl);
    *(uint4*)(base + 2 * TILE_B + off) = pack8(sh);
    *(uint4*)(base + 3 * TILE_B + off) = pack8(sl);
}
__global__ __launch_bounds__(256) void prep_conv(const float* __restrict__ Wc) {
    uint32_t idx = blockIdx.x * 256u + threadIdx.x;   // 4096
    int n7 = idx & 127, kq = (idx >> 7) & 7, c = (idx >> 10) & 1, nb = (idx >> 11) & 1;
    char* base = g_cB + (((size_t)nb * 2 + c) * 2) * TILE_B;
    uint32_t off = swz128((uint32_t)n7 * 128u + (uint32_t)kq * 16u);
    unsigned short hv[8], lv[8];
    #pragma unroll
    for (int e = 0; e < 8; ++e) {
        int k = c * 64 + kq * 8 + e;
        size_t o = (size_t)k * 256 + nb * 128 + n7;
        __nv_bfloat16 h, l;
        split2(Wc[o], h, l); hv[e] = __bfloat16_as_ushort(h); lv[e] = __bfloat16_as_ushort(l);
    }
    *(uint4*)(base + 0 * TILE_B + off) = pack8(hv);
    *(uint4*)(base + 1 * TILE_B + off) = pack8(lv);
}

// ---------------- A-tile fills (128-row tile, SW128) ----------------
__device__ __forceinline__ void fill_A_f32(char* Ah, char* Al, const float* Asrc,
                                           int b, int srow, int fr, int cg,
                                           int c, int shift_chunks, int dil) {
    const int tsh  = (c < shift_chunks) ? dil : 0;
    const int kcol = (c < shift_chunks) ? c * 64 : (c - shift_chunks) * 64;
    const int t = srow - tsh;
    const bool valid = srow >= tsh;
    const float* src = Asrc + ((size_t)(b * T_ + t)) * 64 + kcol + cg;
    #pragma unroll
    for (int j = 0; j < 8; ++j) {
        float4 v = valid ? *(const float4*)(src + j * 4) : make_float4(0.f, 0.f, 0.f, 0.f);
        uint32_t off = swz128((uint32_t)fr * 128u + (uint32_t)(cg + j * 4) * 2u);
        __nv_bfloat16 h0, l0, h1, l1, h2, l2, h3, l3;
        split2(v.x, h0, l0); split2(v.y, h1, l1);
        split2(v.z, h2, l2); split2(v.w, h3, l3);
        uint2 hh, ll;
        hh.x = (uint32_t)__bfloat16_as_ushort(h0) | ((uint32_t)__bfloat16_as_ushort(h1) << 16);
        hh.y = (uint32_t)__bfloat16_as_ushort(h2) | ((uint32_t)__bfloat16_as_ushort(h3) << 16);
        ll.x = (uint32_t)__bfloat16_as_ushort(l0) | ((uint32_t)__bfloat16_as_ushort(l1) << 16);
        ll.y = (uint32_t)__bfloat16_as_ushort(l2) | ((uint32_t)__bfloat16_as_ushort(l3) << 16);
        *(uint2*)(Ah + off) = hh;
        *(uint2*)(Al + off) = ll;
    }
}
__device__ __forceinline__ void fill_A_bf16(char* Ah, char* Al,
                                            const __nv_bfloat16* __restrict__ sh,
                                            const __nv_bfloat16* __restrict__ sl,
                                            int b, int srow, int fr, int cg,
                                            int c, int shift_chunks, int dil) {
    const int tsh  = (c < shift_chunks) ? dil : 0;
    const int kcol = (c < shift_chunks) ? c * 64 : (c - shift_chunks) * 64;
    const int t = srow - tsh;
    const bool valid = srow >= tsh;
    const size_t eoff = ((size_t)(b * T_ + t)) * F_ + kcol + cg;
    const uint4* ph = (const uint4*)(sh + eoff);
    const uint4* pl = (const uint4*)(sl + eoff);
    #pragma unroll
    for (int j = 0; j < 4; ++j) {
        uint4 vh = valid ? ph[j] : make_uint4(0, 0, 0, 0);
        uint4 vl = valid ? pl[j] : make_uint4(0, 0, 0, 0);
        uint32_t off = swz128((uint32_t)fr * 128u + (uint32_t)(cg + j * 8) * 2u);
        *(uint4*)(Ah + off) = vh;
        *(uint4*)(Al + off) = vl;
    }
}

__device__ __forceinline__ void store_hl8(__nv_bfloat16* hd, __nv_bfloat16* ld,
                                          size_t eoff, const float* v) {
    unsigned short hu[8], lu[8];
    #pragma unroll
    for (int e = 0; e < 8; ++e) {
        __nv_bfloat16 h, l; split2(v[e], h, l);
        hu[e] = __bfloat16_as_ushort(h); lu[e] = __bfloat16_as_ushort(l);
    }
    *(uint4*)(hd + eoff) = pack8(hu);
    *(uint4*)(ld + eoff) = pack8(lu);
}
__device__ __forceinline__ void load_hl8(const __nv_bfloat16* hd, const __nv_bfloat16* ld,
                                         size_t eoff, float* v) {
    uint4 hh = *(const uint4*)(hd + eoff);
    uint4 ll = *(const uint4*)(ld + eoff);
    const uint32_t* hp = &hh.x;
    const uint32_t* lp = &ll.x;
    #pragma unroll
    for (int e = 0; e < 4; ++e) {
        __nv_bfloat162 h2 = *(__nv_bfloat162*)&hp[e];
        __nv_bfloat162 l2 = *(__nv_bfloat162*)&lp[e];
        float2 fh = __bfloat1622float2(h2), fl = __bfloat1622float2(l2);
        v[2 * e] = fh.x + fl.x;
        v[2 * e + 1] = fh.y + fl.y;
    }
}
__device__ __forceinline__ float2 dec2(const char* hp, const char* lp, uint32_t off) {
    __nv_bfloat162 h = *(const __nv_bfloat162*)(hp + off);
    __nv_bfloat162 l = *(const __nv_bfloat162*)(lp + off);
    float2 fh = __bfloat1622float2(h), fl = __bfloat1622float2(l);
    return make_float2(fh.x + fl.x, fh.y + fl.y);
}

// ---------------- GEMM layer: M=128/CTA, single-buffered, 2 CTAs/SM ----------------
// mode 0: conv0 (fp32 A) -> outh/l; 1: gated -> zh/zl; 2: res/skip RMW (hi/lo residual)
__global__ __launch_bounds__(256, 2) void mma_layer(
    const float* __restrict__ Af32,
    const __nv_bfloat16* __restrict__ Abh, const __nv_bfloat16* __restrict__ Abl,
    const char* __restrict__ Bbase,
    const float* __restrict__ br, const float* __restrict__ bs,
    int n_chunks, int n_mats, int shift_chunks, int dil, int mode, int first)
{
    extern __shared__ char smem[];
    const int tid = threadIdx.x;
    const int m0 = blockIdx.x * 128;
    const int n0 = blockIdx.y * 128;
    const int b  = m0 / T_;
    const int t0 = m0 % T_;
    const int n_tiles = n_mats * 2;
    const uint32_t bbytes = (uint32_t)n_tiles * TILE_B;
    const int fr = tid >> 1;
    const int cg = (tid & 1) * 32;

#if HAS_TCG
    const uint32_t sbase = smem_u32(smem);
    const int wid = tid >> 5;
    const uint32_t mC  = sbase;        // commit barrier (flips once per chunk)
    const uint32_t bb  = sbase + 8;    // B-copy barrier (flips once per chunk)
    const uint32_t tptr = sbase + 16;
    const uint32_t abase = sbase + 1024;          // A: hi 16KB + lo 16KB
    const uint32_t bsm   = abase + 32768;         // B: 64KB
    char* Ah = smem + 1024;
    char* Al = Ah + TILE_B;

    if (tid == 0) { MBARRIER_INIT(mC, 1); MBARRIER_INIT(bb, 1); }
    if (wid == 0) TCGEN05_ALLOC(tptr, 256);
    __syncthreads();
    uint32_t tmem;
    asm volatile("ld.shared.b32 %0, [%1];" : "=r"(tmem) : "r"(tptr));

    // B(0) DMA immediately (B buffer free)
    if (tid == 0) {
        MBARRIER_EXPECT_TX(bb, bbytes);
        CP_BULK_G2S(bsm, Bbase + ((size_t)(blockIdx.y * n_chunks) * n_tiles) * TILE_B,
                    bbytes, bb);
    }

    for (int c = 0; c < n_chunks; ++c) {
        // A & B bufs free when chunk c-1 committed
        if (c >= 1) {
            MBARRIER_WAIT_PARITY(mC, (c - 1) & 1);
            if (tid == 0) {
                MBARRIER_EXPECT_TX(bb, bbytes);
                CP_BULK_G2S(bsm,
                            Bbase + ((size_t)(blockIdx.y * n_chunks + c) * n_tiles) * TILE_B,
                            bbytes, bb);
            }
        }
        if (mode == 0) fill_A_f32(Ah, Al, Af32, b, t0 + fr, fr, cg, c, shift_chunks, dil);
        else           fill_A_bf16(Ah, Al, Abh, Abl, b, t0 + fr, fr, cg, c, shift_chunks, dil);
        FENCE_PROXY_ASYNC();
        __syncthreads();

        if (wid == 0) {
            MBARRIER_WAIT_PARITY(bb, c & 1);
            if (elect_one_pred()) {
                const uint64_t ah = make_desc(abase);
                const uint64_t al = make_desc(abase + TILE_B);
                for (int mat = 0; mat < n_mats; ++mat) {
                    const uint64_t bh = make_desc(bsm + (uint32_t)(mat * 2) * TILE_B);
                    const uint64_t bl = make_desc(bsm + (uint32_t)(mat * 2 + 1) * TILE_B);
                    const uint32_t dD = tmem + mat * 128;
                    #pragma unroll
                    for (int ks = 0; ks < 4; ++ks)
                        mma_f16(dD, ah + ks * 2, bh + ks * 2, !(c == 0 && ks == 0));
                    #pragma unroll
                    for (int ks = 0; ks < 4; ++ks)
                        mma_f16(dD, ah + ks * 2, bl + ks * 2, 1u);
                    #pragma unroll
                    for (int ks = 0; ks < 4; ++ks)
                        mma_f16(dD, al + ks * 2, bh + ks * 2, 1u);
                }
                TCGEN05_COMMIT(mC);
            }
        }
    }

    MBARRIER_WAIT_PARITY(mC, (n_chunks - 1) & 1);
    TCGEN05_FENCE_AFTER();

    // epilogue: 8 warps; warp w covers subpartition (w&3), column half (w>>2)
    {
        const int lane = tid & 31;
        const int m = m0 + (wid & 3) * 32 + lane;
        const int half = wid >> 2;
        #pragma unroll
        for (int q = 0; q < 4; ++q) {
            const int colc = half * 64 + q * 16;   // 16-col group within mat
            uint32_t rf[16], rg[16];
            TCGEN05_LD_X16(rf, tmem + colc);
            if (n_mats == 2) TCGEN05_LD_X16(rg, tmem + 128 + colc);
            TCGEN05_WAIT_LD();
            const int nc = n0 + colc;
            const size_t rbase = (size_t)m * F_ + nc;
            if (mode == 1) {
                #pragma unroll
                for (int jq = 0; jq < 2; ++jq) {
                    float vv[8];
                    #pragma unroll
                    for (int e = 0; e < 8; ++e)
                        vv[e] = tanhf(__uint_as_float(rf[jq * 8 + e])) *
                                sigmoidf_(__uint_as_float(rg[jq * 8 + e]));
                    store_hl8(g_zh, g_zl, rbase + jq * 8, vv);
                }
            } else if (mode == 0) {
                #pragma unroll
                for (int jq = 0; jq < 2; ++jq) {
                    float vv[8];
                    #pragma unroll
                    for (int e = 0; e < 8; ++e) vv[e] = __uint_as_float(rf[jq * 8 + e]);
                    store_hl8(g_outh, g_outl, rbase + jq * 8, vv);
                }
            } else {
                #pragma unroll
                for (int jq = 0; jq < 2; ++jq) {
                    float vv[8];
                    load_hl8(g_outh, g_outl, rbase + jq * 8, vv);
                    #pragma unroll
                    for (int e = 0; e < 8; ++e) {
                        const size_t off = rbase + jq * 8 + e;
                        const int n = nc + jq * 8 + e;
                        vv[e] += __uint_as_float(rf[jq * 8 + e]) + __ldg(&br[n]);
                        const float sp = first ? 0.0f : g_skip[off];
                        g_skip[off] = sp + __uint_as_float(rg[jq * 8 + e]) + __ldg(&bs[n]);
                    }
                    store_hl8(g_outh, g_outl, rbase + jq * 8, vv);
                }
            }
        }
    }
    __syncthreads();
    if (tid == 0) { MBARRIER_INVAL(mC); MBARRIER_INVAL(bb); }
    if (wid == 0) TCGEN05_DEALLOC(tmem, 256);
#else
    // ---- generic-arch fallback (compile-only; runtime uses sm_103a cubin) ----
    char* Ah = smem;                 // 16KB hi
    char* Al = smem + TILE_B;        // 16KB lo
    char* Bt = smem + 2 * TILE_B;    // 32KB (one mat hi+lo)
    const int ty = tid >> 4, tx = tid & 15;

    for (int mat = 0; mat < n_mats; ++mat) {
        float acc[8][8];
        #pragma unroll
        for (int i = 0; i < 8; ++i)
            #pragma unroll
            for (int j = 0; j < 8; ++j) acc[i][j] = 0.0f;
        for (int c = 0; c < n_chunks; ++c) {
            __syncthreads();
            if (mode == 0) fill_A_f32(Ah, Al, Af32, b, t0 + fr, fr, cg, c, shift_chunks, dil);
            else           fill_A_bf16(Ah, Al, Abh, Abl, b, t0 + fr, fr, cg, c, shift_chunks, dil);
            {
                const char* cb = Bbase + ((size_t)(blockIdx.y * n_chunks + c) * n_tiles) * TILE_B;
                const uint4* srcH = (const uint4*)(cb + (size_t)(mat * 2) * TILE_B);
                const uint4* srcL = (const uint4*)(cb + (size_t)(mat * 2 + 1) * TILE_B);
                uint4* dst = (uint4*)Bt;
                for (int j = tid; j < 1024; j += 256) { dst[j] = srcH[j]; dst[j + 1024] = srcL[j]; }
            }
            __syncthreads();
            #pragma unroll 4
            for (int k2 = 0; k2 < 32; ++k2) {
                float2 a2[8], b2[8];
                #pragma unroll
                for (int i = 0; i < 8; ++i)
                    a2[i] = dec2(Ah, Al, swz128((uint32_t)(ty * 8 + i) * 128u + k2 * 4u));
                #pragma unroll
                for (int j = 0; j < 8; ++j)
                    b2[j] = dec2(Bt, Bt + TILE_B, swz128((uint32_t)(tx * 8 + j) * 128u + k2 * 4u));
                #pragma unroll
                for (int i = 0; i < 8; ++i)
                    #pragma unroll
                    for (int j = 0; j < 8; ++j)
                        acc[i][j] += a2[i].x * b2[j].x + a2[i].y * b2[j].y;
            }
        }
        #pragma unroll
        for (int i = 0; i < 8; ++i) {
            const int m = m0 + ty * 8 + i;
            #pragma unroll
            for (int j = 0; j < 8; ++j) {
                const int n = n0 + tx * 8 + j;
                const size_t off = (size_t)m * F_ + n;
                if (mode == 0) {
                    __nv_bfloat16 h, l; split2(acc[i][j], h, l);
                    g_outh[off] = h; g_outl[off] = l;
                } else if (mode == 1) {
                    if (mat == 0) g_tmp[off] = acc[i][j];
                    else {
                        float z = tanhf(g_tmp[off]) * sigmoidf_(acc[i][j]);
                        __nv_bfloat16 h, l; split2(z, h, l);
                        g_zh[off] = h; g_zl[off] = l;
                    }
                } else {
                    if (mat == 0) {
                        float v = __bfloat162float(g_outh[off]) +
                                  __bfloat162float(g_outl[off]) + acc[i][j] + br[n];
                        __nv_bfloat16 h, l; split2(v, h, l);
                        g_outh[off] = h; g_outl[off] = l;
                    } else {
                        const float sp = first ? 0.0f : g_skip[off];
                        g_skip[off] = sp + acc[i][j] + bs[n];
                    }
                }
            }
        }
    }
#endif
}

// ---------------- head: 32 rows/block, 8 outputs/thread ----------------
__global__ __launch_bounds__(256) void head_kernel(
    const float* __restrict__ Wd1, const float* __restrict__ bd1,
    const float* __restrict__ Wd2, const float* __restrict__ bd2,
    float* __restrict__ y) {
    __shared__ float hs[32][260];
    __shared__ float h2s[32][68];
    const int m0 = blockIdx.x * 32;
    const int r  = threadIdx.x >> 3;
    const int cg = (threadIdx.x & 7) * 8;

    for (int idx = threadIdx.x; idx < 32 * 64; idx += 256) {
        const int row = idx >> 6;
        const int c4  = (idx & 63) * 4;
        float4 v = *(const float4*)&g_skip[(size_t)(m0 + row) * F_ + c4];
        hs[row][c4 + 0] = seluf_(v.x); hs[row][c4 + 1] = seluf_(v.y);
        hs[row][c4 + 2] = seluf_(v.z); hs[row][c4 + 3] = seluf_(v.w);
    }
    __syncthreads();

    float acc[8];
    #pragma unroll
    for (int e = 0; e < 8; ++e) acc[e] = bd1[cg + e];
    #pragma unroll 4
    for (int k = 0; k < 256; ++k) {
        const float h = hs[r][k];
        float4 w0 = __ldg((const float4*)&Wd1[(size_t)k * 64 + cg]);
        float4 w1 = __ldg((const float4*)&Wd1[(size_t)k * 64 + cg + 4]);
        acc[0] += h * w0.x; acc[1] += h * w0.y; acc[2] += h * w0.z; acc[3] += h * w0.w;
        acc[4] += h * w1.x; acc[5] += h * w1.y; acc[6] += h * w1.z; acc[7] += h * w1.w;
    }
    #pragma unroll
    for (int e = 0; e < 8; ++e) h2s[r][cg + e] = seluf_(acc[e]);
    __syncthreads();

    float a2[8];
    #pragma unroll
    for (int e = 0; e < 8; ++e) a2[e] = bd2[cg + e];
    #pragma unroll 4
    for (int k = 0; k < 64; ++k) {
        const float h = h2s[r][k];
        float4 w0 = __ldg((const float4*)&Wd2[(size_t)k * 64 + cg]);
        float4 w1 = __ldg((const float4*)&Wd2[(size_t)k * 64 + cg + 4]);
        a2[0] += h * w0.x; a2[1] += h * w0.y; a2[2] += h * w0.z; a2[3] += h * w0.w;
        a2[4] += h * w1.x; a2[5] += h * w1.y; a2[6] += h * w1.z; a2[7] += h * w1.w;
    }
    float* yp = &y[(size_t)(m0 + r) * 64 + cg];
    *(float4*)yp       = make_float4(a2[0], a2[1], a2[2], a2[3]);
    *(float4*)(yp + 4) = make_float4(a2[4], a2[5], a2[6], a2[7]);
}

// ---------------------------------------------------------------------------
extern "C" void kernel_launch(void* const* d_in, const int* in_sizes, int n_in,
                              void* d_out, int out_size) {
    const float* x   = (const float*)d_in[0];
    const float* Wc  = (const float*)d_in[1];
    const float* Wf  = (const float*)d_in[2];
    const float* Wg  = (const float*)d_in[3];
    const float* Wr  = (const float*)d_in[4];
    const float* br  = (const float*)d_in[5];
    const float* Ws  = (const float*)d_in[6];
    const float* bs  = (const float*)d_in[7];
    const float* Wd1 = (const float*)d_in[8];
    const float* bd1 = (const float*)d_in[9];
    const float* Wd2 = (const float*)d_in[10];
    const float* bd2 = (const float*)d_in[11];
    float* y = (float*)d_out;

    cudaFuncSetAttribute(mma_layer, cudaFuncAttributeMaxDynamicSharedMemorySize, SMEM_BYTES);

    char* gB; cudaGetSymbolAddress((void**)&gB, g_gB);
    char* rB; cudaGetSymbolAddress((void**)&rB, g_rB);
    char* cB; cudaGetSymbolAddress((void**)&cB, g_cB);
    __nv_bfloat16 *oh, *ol, *zh, *zl;
    cudaGetSymbolAddress((void**)&oh, g_outh);
    cudaGetSymbolAddress((void**)&ol, g_outl);
    cudaGetSymbolAddress((void**)&zh, g_zh);
    cudaGetSymbolAddress((void**)&zl, g_zl);

    prep_gated<<<512, 256>>>(Wf, Wg);
    prep_res  <<<256, 256>>>(Wr, Ws);
    prep_conv <<<16,  256>>>(Wc);

    dim3 grid(M_ / 128, 2), blk(256);   // 256 x 2 = 512 CTAs
    mma_layer<<<grid, blk, SMEM_BYTES>>>(x, nullptr, nullptr, cB, nullptr, nullptr,
                                         2, 1, 1, 1, 0, 0);
    for (int i = 0; i < NL; ++i) {
        const int d = 2 << i;
        mma_layer<<<grid, blk, SMEM_BYTES>>>(
            nullptr, oh, ol, gB + (size_t)i * 2 * 8 * 4 * TILE_B, nullptr, nullptr,
            8, 2, 4, d, 1, 0);
        mma_layer<<<grid, blk, SMEM_BYTES>>>(
            nullptr, zh, zl, rB + (size_t)i * 2 * 4 * 4 * TILE_B,
            br + (size_t)i * F_, bs + (size_t)i * F_,
            4, 2, 0, 0, 2, i == 0);
    }
    head_kernel<<<M_ / 32, 256>>>(Wd1, bd1, Wd2, bd2, y);
}

// round 11
// speedup vs baseline: 1.1405x; 1.0601x over previous
#include <cuda_runtime.h>
#include <cuda_bf16.h>
#include <math.h>
#include <stdint.h>

#define B_  8
#define T_  4096
#define F_  256
#define NL  8
#define M_  (B_ * T_)
#define TILE_B 16384
// 1KB header + A single (32KB) + B single (64KB) = 97KB -> 2 CTAs/SM
#define SMEM_BYTES (1024 + 32768 + 65536)

#if defined(__CUDA_ARCH_FEAT_SM103_ALL) || defined(__CUDA_ARCH_FEAT_SM100_ALL) || \
    defined(__CUDA_ARCH_FEAT_SM101_ALL) || defined(__CUDA_ARCH_SPECIFIC__) ||     \
    defined(__CUDA_ARCH_FAMILY_SPECIFIC__)
#define HAS_TCG 1
#else
#define HAS_TCG 0
#endif

__device__ float g_skip[M_ * F_];
__device__ float g_tmp [M_ * F_];  // fallback scratch only
__device__ __nv_bfloat16 g_outh[M_ * F_], g_outl[M_ * F_];
__device__ __nv_bfloat16 g_zh  [M_ * F_], g_zl  [M_ * F_];
// SW128 16KB tiles: per chunk [fh, fl, gh, gl]
__device__ char g_gB[(size_t)NL * 2 * 8 * 4 * TILE_B];
__device__ char g_rB[(size_t)NL * 2 * 4 * 4 * TILE_B];
__device__ char g_cB[(size_t)2 * 2 * 2 * TILE_B];

__host__ __device__ __forceinline__ uint32_t swz128(uint32_t x) { return x ^ ((x >> 3) & 0x70); }
__device__ __forceinline__ float sigmoidf_(float x) { return 1.0f / (1.0f + expf(-x)); }
__device__ __forceinline__ float seluf_(float x) {
    const float sc = 1.0507009873554804934193349852946f;
    const float al = 1.6732632423543772848170429916717f;
    return x > 0.0f ? sc * x : sc * al * (expf(x) - 1.0f);
}
__device__ __forceinline__ void split2(float v, __nv_bfloat16& h, __nv_bfloat16& l) {
    h = __float2bfloat16(v);
    l = __float2bfloat16(v - __bfloat162float(h));
}
__device__ __forceinline__ uint4 pack8(const unsigned short* v) {
    return make_uint4((uint32_t)v[0] | ((uint32_t)v[1] << 16),
                      (uint32_t)v[2] | ((uint32_t)v[3] << 16),
                      (uint32_t)v[4] | ((uint32_t)v[5] << 16),
                      (uint32_t)v[6] | ((uint32_t)v[7] << 16));
}

#if HAS_TCG
__device__ __forceinline__ uint32_t elect_one_pred() {
    uint32_t p_;
    asm volatile("{\n\t.reg .pred p;\n\telect.sync _|p, 0xFFFFFFFF;\n\t"
                 "selp.b32 %0, 1, 0, p;\n\t}" : "=r"(p_));
    return p_;
}
__device__ __forceinline__ uint32_t smem_u32(const void* p) {
    uint32_t a;
    asm("{ .reg .u64 t; cvta.to.shared.u64 t, %1; cvt.u32.u64 %0, t; }" : "=r"(a) : "l"(p));
    return a;
}
#define MBARRIER_INIT(mb, c) \
    asm volatile("mbarrier.init.shared.b64 [%0], %1;" :: "r"((uint32_t)(mb)), "r"((uint32_t)(c)) : "memory")
#define MBARRIER_INVAL(mb) \
    asm volatile("mbarrier.inval.shared.b64 [%0];" :: "r"((uint32_t)(mb)) : "memory")
#define MBARRIER_EXPECT_TX(mb, bytes) \
    asm volatile("mbarrier.arrive.expect_tx.shared.b64 _, [%0], %1;" \
                 :: "r"((uint32_t)(mb)), "r"((uint32_t)(bytes)) : "memory")
#define MBARRIER_WAIT_PARITY(mb, par) do {                                              \
    uint32_t _mb = (uint32_t)(mb), _pa = (uint32_t)(par), _done;                        \
    asm volatile("{\n\t.reg .pred p;\n\t"                                               \
        "mbarrier.try_wait.parity.acquire.cta.shared::cta.b64 p, [%1], %2;\n\t"         \
        "selp.b32 %0, 1, 0, p;\n\t}" : "=r"(_done) : "r"(_mb), "r"(_pa) : "memory");    \
    if (!_done) {                                                                       \
        asm volatile("{\n\t.reg .pred P1;\n\tWL_%=:\n\t"                                \
            "mbarrier.try_wait.parity.acquire.cta.shared::cta.b64 P1, [%0], %1, 0x989680;\n\t" \
            "@P1 bra.uni WD_%=;\n\tbra.uni WL_%=;\n\tWD_%=:\n\t}"                       \
            :: "r"(_mb), "r"(_pa) : "memory");                                          \
    } } while (0)
#define CP_BULK_G2S(dst, src, bytes, mb) \
    asm volatile("cp.async.bulk.shared::cta.global.mbarrier::complete_tx::bytes " \
                 "[%0], [%1], %2, [%3];" \
                 :: "r"((uint32_t)(dst)), "l"(src), "r"((uint32_t)(bytes)), \
                    "r"((uint32_t)(mb)) : "memory")
#define TCGEN05_ALLOC(sa, nc) \
    asm volatile("tcgen05.alloc.cta_group::1.sync.aligned.shared::cta.b32 [%0], %1;" \
                 :: "r"((uint32_t)(sa)), "r"((uint32_t)(nc)) : "memory")
#define TCGEN05_RELINQ() \
    asm volatile("tcgen05.relinquish_alloc_permit.cta_group::1.sync.aligned;")
#define TCGEN05_DEALLOC(tm, nc) \
    asm volatile("tcgen05.dealloc.cta_group::1.sync.aligned.b32 %0, %1;" :: "r"(tm), "r"((uint32_t)(nc)))
#define TCGEN05_COMMIT(mb) \
    asm volatile("tcgen05.commit.cta_group::1.mbarrier::arrive::one.shared::cluster.b64 [%0];" \
                 :: "r"((uint32_t)(mb)) : "memory")
#define TCGEN05_WAIT_LD()     asm volatile("tcgen05.wait::ld.sync.aligned;" ::: "memory")
#define TCGEN05_FENCE_AFTER() asm volatile("tcgen05.fence::after_thread_sync;" ::: "memory")
#define FENCE_PROXY_ASYNC()   asm volatile("fence.proxy.async.shared::cta;" ::: "memory")

#define TCGEN05_LD_X16(r, ta) \
    asm volatile("tcgen05.ld.sync.aligned.32x32b.x16.b32 " \
        "{%0,%1,%2,%3,%4,%5,%6,%7,%8,%9,%10,%11,%12,%13,%14,%15}, [%16];" \
        : "=r"((r)[0]),"=r"((r)[1]),"=r"((r)[2]),"=r"((r)[3]), \
          "=r"((r)[4]),"=r"((r)[5]),"=r"((r)[6]),"=r"((r)[7]), \
          "=r"((r)[8]),"=r"((r)[9]),"=r"((r)[10]),"=r"((r)[11]), \
          "=r"((r)[12]),"=r"((r)[13]),"=r"((r)[14]),"=r"((r)[15]) : "r"(ta))

static __device__ __forceinline__ uint64_t make_desc(uint32_t addr) {
    const uint64_t BASE = (uint64_t(2) << 61) | (uint64_t(1) << 46) |
                          (uint64_t(64) << 32) | (uint64_t(1) << 16);
    return BASE | ((uint64_t)(addr >> 4) & 0x3FFF);
}
#define IDESC_ ((1u << 4) | (1u << 7) | (1u << 10) | (16u << 17) | (8u << 24))

__device__ __forceinline__ void mma_f16(uint32_t d, uint64_t a, uint64_t b, uint32_t en) {
    asm volatile("{\n\t.reg .pred p;\n\tsetp.ne.u32 p, %3, 0;\n\t"
        "tcgen05.mma.cta_group::1.kind::f16 [%0], %1, %2, %4, {%5,%5,%5,%5}, p;\n\t}"
        :: "r"(d), "l"(a), "l"(b), "r"(en), "r"(IDESC_), "r"(0u) : "memory");
}
#endif  // HAS_TCG

// ---------------- weight preprocessing (coalesced 16B writes) ----------------
__global__ __launch_bounds__(256) void prep_gated(const float* __restrict__ Wf,
                                                  const float* __restrict__ Wg) {
    uint32_t idx = blockIdx.x * 256u + threadIdx.x;   // 2^17
    int n7 = idx & 127, kq = (idx >> 7) & 7, c = (idx >> 10) & 7;
    int nb = (idx >> 13) & 1, i = idx >> 14;
    char* base = g_gB + (((size_t)(i * 2 + nb) * 8 + c) * 4) * TILE_B;
    uint32_t off = swz128((uint32_t)n7 * 128u + (uint32_t)kq * 16u);
    unsigned short fh[8], fl[8], gh[8], gl[8];
    #pragma unroll
    for (int e = 0; e < 8; ++e) {
        int k = c * 64 + kq * 8 + e;
        size_t o = (size_t)i * 131072 + (size_t)k * 256 + nb * 128 + n7;
        __nv_bfloat16 h, l;
        split2(Wf[o], h, l); fh[e] = __bfloat16_as_ushort(h); fl[e] = __bfloat16_as_ushort(l);
        split2(Wg[o], h, l); gh[e] = __bfloat16_as_ushort(h); gl[e] = __bfloat16_as_ushort(l);
    }
    *(uint4*)(base + 0 * TILE_B + off) = pack8(fh);
    *(uint4*)(base + 1 * TILE_B + off) = pack8(fl);
    *(uint4*)(base + 2 * TILE_B + off) = pack8(gh);
    *(uint4*)(base + 3 * TILE_B + off) = pack8(gl);
}
__global__ __launch_bounds__(256) void prep_res(const float* __restrict__ Wr,
                                                const float* __restrict__ Ws) {
    uint32_t idx = blockIdx.x * 256u + threadIdx.x;   // 2^16
    int n7 = idx & 127, kq = (idx >> 7) & 7, c = (idx >> 10) & 3;
    int nb = (idx >> 12) & 1, i = idx >> 13;
    char* base = g_rB + (((size_t)(i * 2 + nb) * 4 + c) * 4) * TILE_B;
    uint32_t off = swz128((uint32_t)n7 * 128u + (uint32_t)kq * 16u);
    unsigned short rh[8], rl[8], sh[8], sl[8];
    #pragma unroll
    for (int e = 0; e < 8; ++e) {
        int k = c * 64 + kq * 8 + e;
        size_t o = (size_t)i * 65536 + (size_t)k * 256 + nb * 128 + n7;
        __nv_bfloat16 h, l;
        split2(Wr[o], h, l); rh[e] = __bfloat16_as_ushort(h); rl[e] = __bfloat16_as_ushort(l);
        split2(Ws[o], h, l); sh[e] = __bfloat16_as_ushort(h); sl[e] = __bfloat16_as_ushort(l);
    }
    *(uint4*)(base + 0 * TILE_B + off) = pack8(rh);
    *(uint4*)(base + 1 * TILE_B + off) = pack8(rl);
    *(uint4*)(base + 2 * TILE_B + off) = pack8(sh);
    *(uint4*)(base + 3 * TILE_B + off) = pack8(sl);
}
__global__ __launch_bounds__(256) void prep_conv(const float* __restrict__ Wc) {
    uint32_t idx = blockIdx.x * 256u + threadIdx.x;   // 4096
    int n7 = idx & 127, kq = (idx >> 7) & 7, c = (idx >> 10) & 1, nb = (idx >> 11) & 1;
    char* base = g_cB + (((size_t)nb * 2 + c) * 2) * TILE_B;
    uint32_t off = swz128((uint32_t)n7 * 128u + (uint32_t)kq * 16u);
    unsigned short hv[8], lv[8];
    #pragma unroll
    for (int e = 0; e < 8; ++e) {
        int k = c * 64 + kq * 8 + e;
        size_t o = (size_t)k * 256 + nb * 128 + n7;
        __nv_bfloat16 h, l;
        split2(Wc[o], h, l); hv[e] = __bfloat16_as_ushort(h); lv[e] = __bfloat16_as_ushort(l);
    }
    *(uint4*)(base + 0 * TILE_B + off) = pack8(hv);
    *(uint4*)(base + 1 * TILE_B + off) = pack8(lv);
}

// ---------------- A-tile fills (128-row tile, SW128) ----------------
__device__ __forceinline__ void fill_A_f32(char* Ah, char* Al, const float* Asrc,
                                           int b, int srow, int fr, int cg,
                                           int c, int shift_chunks, int dil) {
    const int tsh  = (c < shift_chunks) ? dil : 0;
    const int kcol = (c < shift_chunks) ? c * 64 : (c - shift_chunks) * 64;
    const int t = srow - tsh;
    const bool valid = srow >= tsh;
    const float* src = Asrc + ((size_t)(b * T_ + t)) * 64 + kcol + cg;
    #pragma unroll
    for (int j = 0; j < 8; ++j) {
        float4 v = valid ? *(const float4*)(src + j * 4) : make_float4(0.f, 0.f, 0.f, 0.f);
        uint32_t off = swz128((uint32_t)fr * 128u + (uint32_t)(cg + j * 4) * 2u);
        __nv_bfloat16 h0, l0, h1, l1, h2, l2, h3, l3;
        split2(v.x, h0, l0); split2(v.y, h1, l1);
        split2(v.z, h2, l2); split2(v.w, h3, l3);
        uint2 hh, ll;
        hh.x = (uint32_t)__bfloat16_as_ushort(h0) | ((uint32_t)__bfloat16_as_ushort(h1) << 16);
        hh.y = (uint32_t)__bfloat16_as_ushort(h2) | ((uint32_t)__bfloat16_as_ushort(h3) << 16);
        ll.x = (uint32_t)__bfloat16_as_ushort(l0) | ((uint32_t)__bfloat16_as_ushort(l1) << 16);
        ll.y = (uint32_t)__bfloat16_as_ushort(l2) | ((uint32_t)__bfloat16_as_ushort(l3) << 16);
        *(uint2*)(Ah + off) = hh;
        *(uint2*)(Al + off) = ll;
    }
}
__device__ __forceinline__ void fill_A_bf16(char* Ah, char* Al,
                                            const __nv_bfloat16* __restrict__ sh,
                                            const __nv_bfloat16* __restrict__ sl,
                                            int b, int srow, int fr, int cg,
                                            int c, int shift_chunks, int dil) {
    const int tsh  = (c < shift_chunks) ? dil : 0;
    const int kcol = (c < shift_chunks) ? c * 64 : (c - shift_chunks) * 64;
    const int t = srow - tsh;
    const bool valid = srow >= tsh;
    const size_t eoff = ((size_t)(b * T_ + t)) * F_ + kcol + cg;
    const uint4* ph = (const uint4*)(sh + eoff);
    const uint4* pl = (const uint4*)(sl + eoff);
    #pragma unroll
    for (int j = 0; j < 4; ++j) {
        uint4 vh = valid ? ph[j] : make_uint4(0, 0, 0, 0);
        uint4 vl = valid ? pl[j] : make_uint4(0, 0, 0, 0);
        uint32_t off = swz128((uint32_t)fr * 128u + (uint32_t)(cg + j * 8) * 2u);
        *(uint4*)(Ah + off) = vh;
        *(uint4*)(Al + off) = vl;
    }
}

__device__ __forceinline__ void store_hl8(__nv_bfloat16* hd, __nv_bfloat16* ld,
                                          size_t eoff, const float* v) {
    unsigned short hu[8], lu[8];
    #pragma unroll
    for (int e = 0; e < 8; ++e) {
        __nv_bfloat16 h, l; split2(v[e], h, l);
        hu[e] = __bfloat16_as_ushort(h); lu[e] = __bfloat16_as_ushort(l);
    }
    *(uint4*)(hd + eoff) = pack8(hu);
    *(uint4*)(ld + eoff) = pack8(lu);
}
__device__ __forceinline__ void load_hl8(const __nv_bfloat16* hd, const __nv_bfloat16* ld,
                                         size_t eoff, float* v) {
    uint4 hh = *(const uint4*)(hd + eoff);
    uint4 ll = *(const uint4*)(ld + eoff);
    const uint32_t* hp = &hh.x;
    const uint32_t* lp = &ll.x;
    #pragma unroll
    for (int e = 0; e < 4; ++e) {
        __nv_bfloat162 h2 = *(__nv_bfloat162*)&hp[e];
        __nv_bfloat162 l2 = *(__nv_bfloat162*)&lp[e];
        float2 fh = __bfloat1622float2(h2), fl = __bfloat1622float2(l2);
        v[2 * e] = fh.x + fl.x;
        v[2 * e + 1] = fh.y + fl.y;
    }
}
__device__ __forceinline__ float2 dec2(const char* hp, const char* lp, uint32_t off) {
    __nv_bfloat162 h = *(const __nv_bfloat162*)(hp + off);
    __nv_bfloat162 l = *(const __nv_bfloat162*)(lp + off);
    float2 fh = __bfloat1622float2(h), fl = __bfloat1622float2(l);
    return make_float2(fh.x + fl.x, fh.y + fl.y);
}

// ---------------- GEMM layer: M=128/CTA, single-buffered, 2 CTAs/SM ----------------
// mode 0: conv0 (fp32 A) -> outh/l; 1: gated -> zh/zl; 2: res/skip RMW (hi/lo residual)
__global__ __launch_bounds__(256, 2) void mma_layer(
    const float* __restrict__ Af32,
    const __nv_bfloat16* __restrict__ Abh, const __nv_bfloat16* __restrict__ Abl,
    const char* __restrict__ Bbase,
    const float* __restrict__ br, const float* __restrict__ bs,
    int n_chunks, int n_mats, int shift_chunks, int dil, int mode, int first)
{
    extern __shared__ char smem[];
    const int tid = threadIdx.x;
    const int m0 = blockIdx.x * 128;
    const int n0 = blockIdx.y * 128;
    const int b  = m0 / T_;
    const int t0 = m0 % T_;
    const int n_tiles = n_mats * 2;
    const uint32_t bbytes = (uint32_t)n_tiles * TILE_B;
    const int fr = tid >> 1;
    const int cg = (tid & 1) * 32;

#if HAS_TCG
    const uint32_t sbase = smem_u32(smem);
    const int wid = tid >> 5;
    const uint32_t mC  = sbase;        // commit barrier (flips once per chunk)
    const uint32_t bb  = sbase + 8;    // B-copy barrier (flips once per chunk)
    const uint32_t tptr = sbase + 16;
    const uint32_t abase = sbase + 1024;          // A: hi 16KB + lo 16KB
    const uint32_t bsm   = abase + 32768;         // B: 64KB
    char* Ah = smem + 1024;
    char* Al = Ah + TILE_B;

    if (tid == 0) { MBARRIER_INIT(mC, 1); MBARRIER_INIT(bb, 1); }
    if (wid == 0) {
        TCGEN05_ALLOC(tptr, 256);
        TCGEN05_RELINQ();   // let the co-resident CTA allocate too
    }
    __syncthreads();
    uint32_t tmem;
    asm volatile("ld.shared.b32 %0, [%1];" : "=r"(tmem) : "r"(tptr));

    // B(0) DMA immediately (B buffer free)
    if (tid == 0) {
        MBARRIER_EXPECT_TX(bb, bbytes);
        CP_BULK_G2S(bsm, Bbase + ((size_t)(blockIdx.y * n_chunks) * n_tiles) * TILE_B,
                    bbytes, bb);
    }

    for (int c = 0; c < n_chunks; ++c) {
        // A & B bufs free when chunk c-1 committed
        if (c >= 1) {
            MBARRIER_WAIT_PARITY(mC, (c - 1) & 1);
            if (tid == 0) {
                MBARRIER_EXPECT_TX(bb, bbytes);
                CP_BULK_G2S(bsm,
                            Bbase + ((size_t)(blockIdx.y * n_chunks + c) * n_tiles) * TILE_B,
                            bbytes, bb);
            }
        }
        if (mode == 0) fill_A_f32(Ah, Al, Af32, b, t0 + fr, fr, cg, c, shift_chunks, dil);
        else           fill_A_bf16(Ah, Al, Abh, Abl, b, t0 + fr, fr, cg, c, shift_chunks, dil);
        FENCE_PROXY_ASYNC();
        __syncthreads();

        if (wid == 0) {
            MBARRIER_WAIT_PARITY(bb, c & 1);
            if (elect_one_pred()) {
                const uint64_t ah = make_desc(abase);
                const uint64_t al = make_desc(abase + TILE_B);
                for (int mat = 0; mat < n_mats; ++mat) {
                    const uint64_t bh = make_desc(bsm + (uint32_t)(mat * 2) * TILE_B);
                    const uint64_t bl = make_desc(bsm + (uint32_t)(mat * 2 + 1) * TILE_B);
                    const uint32_t dD = tmem + mat * 128;
                    #pragma unroll
                    for (int ks = 0; ks < 4; ++ks)
                        mma_f16(dD, ah + ks * 2, bh + ks * 2, !(c == 0 && ks == 0));
                    #pragma unroll
                    for (int ks = 0; ks < 4; ++ks)
                        mma_f16(dD, ah + ks * 2, bl + ks * 2, 1u);
                    #pragma unroll
                    for (int ks = 0; ks < 4; ++ks)
                        mma_f16(dD, al + ks * 2, bh + ks * 2, 1u);
                }
                TCGEN05_COMMIT(mC);
            }
        }
    }

    MBARRIER_WAIT_PARITY(mC, (n_chunks - 1) & 1);
    TCGEN05_FENCE_AFTER();

    // epilogue: 8 warps; warp w covers subpartition (w&3), column half (w>>2)
    {
        const int lane = tid & 31;
        const int m = m0 + (wid & 3) * 32 + lane;
        const int half = wid >> 2;
        #pragma unroll
        for (int q = 0; q < 4; ++q) {
            const int colc = half * 64 + q * 16;   // 16-col group within mat
            uint32_t rf[16], rg[16];
            TCGEN05_LD_X16(rf, tmem + colc);
            if (n_mats == 2) TCGEN05_LD_X16(rg, tmem + 128 + colc);
            TCGEN05_WAIT_LD();
            const int nc = n0 + colc;
            const size_t rbase = (size_t)m * F_ + nc;
            if (mode == 1) {
                #pragma unroll
                for (int jq = 0; jq < 2; ++jq) {
                    float vv[8];
                    #pragma unroll
                    for (int e = 0; e < 8; ++e)
                        vv[e] = tanhf(__uint_as_float(rf[jq * 8 + e])) *
                                sigmoidf_(__uint_as_float(rg[jq * 8 + e]));
                    store_hl8(g_zh, g_zl, rbase + jq * 8, vv);
                }
            } else if (mode == 0) {
                #pragma unroll
                for (int jq = 0; jq < 2; ++jq) {
                    float vv[8];
                    #pragma unroll
                    for (int e = 0; e < 8; ++e) vv[e] = __uint_as_float(rf[jq * 8 + e]);
                    store_hl8(g_outh, g_outl, rbase + jq * 8, vv);
                }
            } else {
                #pragma unroll
                for (int jq = 0; jq < 2; ++jq) {
                    float vv[8];
                    load_hl8(g_outh, g_outl, rbase + jq * 8, vv);
                    #pragma unroll
                    for (int e = 0; e < 8; ++e) {
                        const size_t off = rbase + jq * 8 + e;
                        const int n = nc + jq * 8 + e;
                        vv[e] += __uint_as_float(rf[jq * 8 + e]) + __ldg(&br[n]);
                        const float sp = first ? 0.0f : g_skip[off];
                        g_skip[off] = sp + __uint_as_float(rg[jq * 8 + e]) + __ldg(&bs[n]);
                    }
                    store_hl8(g_outh, g_outl, rbase + jq * 8, vv);
                }
            }
        }
    }
    __syncthreads();
    if (tid == 0) { MBARRIER_INVAL(mC); MBARRIER_INVAL(bb); }
    if (wid == 0) TCGEN05_DEALLOC(tmem, 256);
#else
    // ---- generic-arch fallback (compile-only; runtime uses sm_103a cubin) ----
    char* Ah = smem;                 // 16KB hi
    char* Al = smem + TILE_B;        // 16KB lo
    char* Bt = smem + 2 * TILE_B;    // 32KB (one mat hi+lo)
    const int ty = tid >> 4, tx = tid & 15;

    for (int mat = 0; mat < n_mats; ++mat) {
        float acc[8][8];
        #pragma unroll
        for (int i = 0; i < 8; ++i)
            #pragma unroll
            for (int j = 0; j < 8; ++j) acc[i][j] = 0.0f;
        for (int c = 0; c < n_chunks; ++c) {
            __syncthreads();
            if (mode == 0) fill_A_f32(Ah, Al, Af32, b, t0 + fr, fr, cg, c, shift_chunks, dil);
            else           fill_A_bf16(Ah, Al, Abh, Abl, b, t0 + fr, fr, cg, c, shift_chunks, dil);
            {
                const char* cb = Bbase + ((size_t)(blockIdx.y * n_chunks + c) * n_tiles) * TILE_B;
                const uint4* srcH = (const uint4*)(cb + (size_t)(mat * 2) * TILE_B);
                const uint4* srcL = (const uint4*)(cb + (size_t)(mat * 2 + 1) * TILE_B);
                uint4* dst = (uint4*)Bt;
                for (int j = tid; j < 1024; j += 256) { dst[j] = srcH[j]; dst[j + 1024] = srcL[j]; }
            }
            __syncthreads();
            #pragma unroll 4
            for (int k2 = 0; k2 < 32; ++k2) {
                float2 a2[8], b2[8];
                #pragma unroll
                for (int i = 0; i < 8; ++i)
                    a2[i] = dec2(Ah, Al, swz128((uint32_t)(ty * 8 + i) * 128u + k2 * 4u));
                #pragma unroll
                for (int j = 0; j < 8; ++j)
                    b2[j] = dec2(Bt, Bt + TILE_B, swz128((uint32_t)(tx * 8 + j) * 128u + k2 * 4u));
                #pragma unroll
                for (int i = 0; i < 8; ++i)
                    #pragma unroll
                    for (int j = 0; j < 8; ++j)
                        acc[i][j] += a2[i].x * b2[j].x + a2[i].y * b2[j].y;
            }
        }
        #pragma unroll
        for (int i = 0; i < 8; ++i) {
            const int m = m0 + ty * 8 + i;
            #pragma unroll
            for (int j = 0; j < 8; ++j) {
                const int n = n0 + tx * 8 + j;
                const size_t off = (size_t)m * F_ + n;
                if (mode == 0) {
                    __nv_bfloat16 h, l; split2(acc[i][j], h, l);
                    g_outh[off] = h; g_outl[off] = l;
                } else if (mode == 1) {
                    if (mat == 0) g_tmp[off] = acc[i][j];
                    else {
                        float z = tanhf(g_tmp[off]) * sigmoidf_(acc[i][j]);
                        __nv_bfloat16 h, l; split2(z, h, l);
                        g_zh[off] = h; g_zl[off] = l;
                    }
                } else {
                    if (mat == 0) {
                        float v = __bfloat162float(g_outh[off]) +
                                  __bfloat162float(g_outl[off]) + acc[i][j] + br[n];
                        __nv_bfloat16 h, l; split2(v, h, l);
                        g_outh[off] = h; g_outl[off] = l;
                    } else {
                        const float sp = first ? 0.0f : g_skip[off];
                        g_skip[off] = sp + acc[i][j] + bs[n];
                    }
                }
            }
        }
    }
#endif
}

// ---------------- head: 32 rows/block, 8 outputs/thread ----------------
__global__ __launch_bounds__(256) void head_kernel(
    const float* __restrict__ Wd1, const float* __restrict__ bd1,
    const float* __restrict__ Wd2, const float* __restrict__ bd2,
    float* __restrict__ y) {
    __shared__ float hs[32][260];
    __shared__ float h2s[32][68];
    const int m0 = blockIdx.x * 32;
    const int r  = threadIdx.x >> 3;
    const int cg = (threadIdx.x & 7) * 8;

    for (int idx = threadIdx.x; idx < 32 * 64; idx += 256) {
        const int row = idx >> 6;
        const int c4  = (idx & 63) * 4;
        float4 v = *(const float4*)&g_skip[(size_t)(m0 + row) * F_ + c4];
        hs[row][c4 + 0] = seluf_(v.x); hs[row][c4 + 1] = seluf_(v.y);
        hs[row][c4 + 2] = seluf_(v.z); hs[row][c4 + 3] = seluf_(v.w);
    }
    __syncthreads();

    float acc[8];
    #pragma unroll
    for (int e = 0; e < 8; ++e) acc[e] = bd1[cg + e];
    #pragma unroll 4
    for (int k = 0; k < 256; ++k) {
        const float h = hs[r][k];
        float4 w0 = __ldg((const float4*)&Wd1[(size_t)k * 64 + cg]);
        float4 w1 = __ldg((const float4*)&Wd1[(size_t)k * 64 + cg + 4]);
        acc[0] += h * w0.x; acc[1] += h * w0.y; acc[2] += h * w0.z; acc[3] += h * w0.w;
        acc[4] += h * w1.x; acc[5] += h * w1.y; acc[6] += h * w1.z; acc[7] += h * w1.w;
    }
    #pragma unroll
    for (int e = 0; e < 8; ++e) h2s[r][cg + e] = seluf_(acc[e]);
    __syncthreads();

    float a2[8];
    #pragma unroll
    for (int e = 0; e < 8; ++e) a2[e] = bd2[cg + e];
    #pragma unroll 4
    for (int k = 0; k < 64; ++k) {
        const float h = h2s[r][k];
        float4 w0 = __ldg((const float4*)&Wd2[(size_t)k * 64 + cg]);
        float4 w1 = __ldg((const float4*)&Wd2[(size_t)k * 64 + cg + 4]);
        a2[0] += h * w0.x; a2[1] += h * w0.y; a2[2] += h * w0.z; a2[3] += h * w0.w;
        a2[4] += h * w1.x; a2[5] += h * w1.y; a2[6] += h * w1.z; a2[7] += h * w1.w;
    }
    float* yp = &y[(size_t)(m0 + r) * 64 + cg];
    *(float4*)yp       = make_float4(a2[0], a2[1], a2[2], a2[3]);
    *(float4*)(yp + 4) = make_float4(a2[4], a2[5], a2[6], a2[7]);
}

// ---------------------------------------------------------------------------
extern "C" void kernel_launch(void* const* d_in, const int* in_sizes, int n_in,
                              void* d_out, int out_size) {
    const float* x   = (const float*)d_in[0];
    const float* Wc  = (const float*)d_in[1];
    const float* Wf  = (const float*)d_in[2];
    const float* Wg  = (const float*)d_in[3];
    const float* Wr  = (const float*)d_in[4];
    const float* br  = (const float*)d_in[5];
    const float* Ws  = (const float*)d_in[6];
    const float* bs  = (const float*)d_in[7];
    const float* Wd1 = (const float*)d_in[8];
    const float* bd1 = (const float*)d_in[9];
    const float* Wd2 = (const float*)d_in[10];
    const float* bd2 = (const float*)d_in[11];
    float* y = (float*)d_out;

    cudaFuncSetAttribute(mma_layer, cudaFuncAttributeMaxDynamicSharedMemorySize, SMEM_BYTES);
    // Max L1/smem carveout so TWO 97KB CTAs can co-reside per SM.
    cudaFuncSetAttribute(mma_layer, cudaFuncAttributePreferredSharedMemoryCarveout, 100);

    char* gB; cudaGetSymbolAddress((void**)&gB, g_gB);
    char* rB; cudaGetSymbolAddress((void**)&rB, g_rB);
    char* cB; cudaGetSymbolAddress((void**)&cB, g_cB);
    __nv_bfloat16 *oh, *ol, *zh, *zl;
    cudaGetSymbolAddress((void**)&oh, g_outh);
    cudaGetSymbolAddress((void**)&ol, g_outl);
    cudaGetSymbolAddress((void**)&zh, g_zh);
    cudaGetSymbolAddress((void**)&zl, g_zl);

    prep_gated<<<512, 256>>>(Wf, Wg);
    prep_res  <<<256, 256>>>(Wr, Ws);
    prep_conv <<<16,  256>>>(Wc);

    dim3 grid(M_ / 128, 2), blk(256);   // 256 x 2 = 512 CTAs
    mma_layer<<<grid, blk, SMEM_BYTES>>>(x, nullptr, nullptr, cB, nullptr, nullptr,
                                         2, 1, 1, 1, 0, 0);
    for (int i = 0; i < NL; ++i) {
        const int d = 2 << i;
        mma_layer<<<grid, blk, SMEM_BYTES>>>(
            nullptr, oh, ol, gB + (size_t)i * 2 * 8 * 4 * TILE_B, nullptr, nullptr,
            8, 2, 4, d, 1, 0);
        mma_layer<<<grid, blk, SMEM_BYTES>>>(
            nullptr, zh, zl, rB + (size_t)i * 2 * 4 * 4 * TILE_B,
            br + (size_t)i * F_, bs + (size_t)i * F_,
            4, 2, 0, 0, 2, i == 0);
    }
    head_kernel<<<M_ / 32, 256>>>(Wd1, bd1, Wd2, bd2, y);
}

// round 12
// speedup vs baseline: 1.1564x; 1.0139x over previous
#include <cuda_runtime.h>
#include <cuda_bf16.h>
#include <math.h>
#include <stdint.h>

#define B_  8
#define T_  4096
#define F_  256
#define NL  8
#define M_  (B_ * T_)
#define TILE_B 16384
#define SMEM_BYTES (1024 + 32768 + 65536)

#if defined(__CUDA_ARCH_FEAT_SM103_ALL) || defined(__CUDA_ARCH_FEAT_SM100_ALL) || \
    defined(__CUDA_ARCH_FEAT_SM101_ALL) || defined(__CUDA_ARCH_SPECIFIC__) ||     \
    defined(__CUDA_ARCH_FAMILY_SPECIFIC__)
#define HAS_TCG 1
#else
#define HAS_TCG 0
#endif

__device__ float g_skip[M_ * F_];
__device__ float g_tmp [M_ * F_];  // fallback scratch only
__device__ __nv_bfloat16 g_outh[M_ * F_], g_outl[M_ * F_];
__device__ __nv_bfloat16 g_zh  [M_ * F_], g_zl  [M_ * F_];
__device__ char g_gB[(size_t)NL * 2 * 8 * 4 * TILE_B];
__device__ char g_rB[(size_t)NL * 2 * 4 * 4 * TILE_B];
__device__ char g_cB[(size_t)2 * 2 * 2 * TILE_B];

__host__ __device__ __forceinline__ uint32_t swz128(uint32_t x) { return x ^ ((x >> 3) & 0x70); }
__device__ __forceinline__ float seluf_(float x) {
    const float sc = 1.0507009873554804934193349852946f;
    const float al = 1.6732632423543772848170429916717f;
    return x > 0.0f ? sc * x : sc * al * (expf(x) - 1.0f);
}
// fast gated activation: tanh(f)*sigmoid(g) via MUFU ex2/rcp (abs err ~1e-7)
__device__ __forceinline__ float gate_fast(float f, float g) {
    float ef = __expf(-2.0f * f);
    float t  = __fdividef(1.0f - ef, 1.0f + ef);
    float s  = __fdividef(1.0f, 1.0f + __expf(-g));
    return t * s;
}
__device__ __forceinline__ void split2(float v, __nv_bfloat16& h, __nv_bfloat16& l) {
    h = __float2bfloat16(v);
    l = __float2bfloat16(v - __bfloat162float(h));
}
__device__ __forceinline__ uint4 pack8(const unsigned short* v) {
    return make_uint4((uint32_t)v[0] | ((uint32_t)v[1] << 16),
                      (uint32_t)v[2] | ((uint32_t)v[3] << 16),
                      (uint32_t)v[4] | ((uint32_t)v[5] << 16),
                      (uint32_t)v[6] | ((uint32_t)v[7] << 16));
}

#if HAS_TCG
__device__ __forceinline__ uint32_t elect_one_pred() {
    uint32_t p_;
    asm volatile("{\n\t.reg .pred p;\n\telect.sync _|p, 0xFFFFFFFF;\n\t"
                 "selp.b32 %0, 1, 0, p;\n\t}" : "=r"(p_));
    return p_;
}
__device__ __forceinline__ uint32_t smem_u32(const void* p) {
    uint32_t a;
    asm("{ .reg .u64 t; cvta.to.shared.u64 t, %1; cvt.u32.u64 %0, t; }" : "=r"(a) : "l"(p));
    return a;
}
#define MBARRIER_INIT(mb, c) \
    asm volatile("mbarrier.init.shared.b64 [%0], %1;" :: "r"((uint32_t)(mb)), "r"((uint32_t)(c)) : "memory")
#define MBARRIER_INVAL(mb) \
    asm volatile("mbarrier.inval.shared.b64 [%0];" :: "r"((uint32_t)(mb)) : "memory")
#define MBARRIER_EXPECT_TX(mb, bytes) \
    asm volatile("mbarrier.arrive.expect_tx.shared.b64 _, [%0], %1;" \
                 :: "r"((uint32_t)(mb)), "r"((uint32_t)(bytes)) : "memory")
#define MBARRIER_WAIT_PARITY(mb, par) do {                                              \
    uint32_t _mb = (uint32_t)(mb), _pa = (uint32_t)(par), _done;                        \
    asm volatile("{\n\t.reg .pred p;\n\t"                                               \
        "mbarrier.try_wait.parity.acquire.cta.shared::cta.b64 p, [%1], %2;\n\t"         \
        "selp.b32 %0, 1, 0, p;\n\t}" : "=r"(_done) : "r"(_mb), "r"(_pa) : "memory");    \
    if (!_done) {                                                                       \
        asm volatile("{\n\t.reg .pred P1;\n\tWL_%=:\n\t"                                \
            "mbarrier.try_wait.parity.acquire.cta.shared::cta.b64 P1, [%0], %1, 0x989680;\n\t" \
            "@P1 bra.uni WD_%=;\n\tbra.uni WL_%=;\n\tWD_%=:\n\t}"                       \
            :: "r"(_mb), "r"(_pa) : "memory");                                          \
    } } while (0)
#define CP_BULK_G2S(dst, src, bytes, mb) \
    asm volatile("cp.async.bulk.shared::cta.global.mbarrier::complete_tx::bytes " \
                 "[%0], [%1], %2, [%3];" \
                 :: "r"((uint32_t)(dst)), "l"(src), "r"((uint32_t)(bytes)), \
                    "r"((uint32_t)(mb)) : "memory")
#define TCGEN05_ALLOC(sa, nc) \
    asm volatile("tcgen05.alloc.cta_group::1.sync.aligned.shared::cta.b32 [%0], %1;" \
                 :: "r"((uint32_t)(sa)), "r"((uint32_t)(nc)) : "memory")
#define TCGEN05_RELINQ() \
    asm volatile("tcgen05.relinquish_alloc_permit.cta_group::1.sync.aligned;")
#define TCGEN05_DEALLOC(tm, nc) \
    asm volatile("tcgen05.dealloc.cta_group::1.sync.aligned.b32 %0, %1;" :: "r"(tm), "r"((uint32_t)(nc)))
#define TCGEN05_COMMIT(mb) \
    asm volatile("tcgen05.commit.cta_group::1.mbarrier::arrive::one.shared::cluster.b64 [%0];" \
                 :: "r"((uint32_t)(mb)) : "memory")
#define TCGEN05_WAIT_LD()     asm volatile("tcgen05.wait::ld.sync.aligned;" ::: "memory")
#define TCGEN05_FENCE_AFTER() asm volatile("tcgen05.fence::after_thread_sync;" ::: "memory")
#define FENCE_PROXY_ASYNC()   asm volatile("fence.proxy.async.shared::cta;" ::: "memory")

#define TCGEN05_LD_X16(r, ta) \
    asm volatile("tcgen05.ld.sync.aligned.32x32b.x16.b32 " \
        "{%0,%1,%2,%3,%4,%5,%6,%7,%8,%9,%10,%11,%12,%13,%14,%15}, [%16];" \
        : "=r"((r)[0]),"=r"((r)[1]),"=r"((r)[2]),"=r"((r)[3]), \
          "=r"((r)[4]),"=r"((r)[5]),"=r"((r)[6]),"=r"((r)[7]), \
          "=r"((r)[8]),"=r"((r)[9]),"=r"((r)[10]),"=r"((r)[11]), \
          "=r"((r)[12]),"=r"((r)[13]),"=r"((r)[14]),"=r"((r)[15]) : "r"(ta))

static __device__ __forceinline__ uint64_t make_desc(uint32_t addr) {
    const uint64_t BASE = (uint64_t(2) << 61) | (uint64_t(1) << 46) |
                          (uint64_t(64) << 32) | (uint64_t(1) << 16);
    return BASE | ((uint64_t)(addr >> 4) & 0x3FFF);
}
#define IDESC_ ((1u << 4) | (1u << 7) | (1u << 10) | (16u << 17) | (8u << 24))

__device__ __forceinline__ void mma_f16(uint32_t d, uint64_t a, uint64_t b, uint32_t en) {
    asm volatile("{\n\t.reg .pred p;\n\tsetp.ne.u32 p, %3, 0;\n\t"
        "tcgen05.mma.cta_group::1.kind::f16 [%0], %1, %2, %4, {%5,%5,%5,%5}, p;\n\t}"
        :: "r"(d), "l"(a), "l"(b), "r"(en), "r"(IDESC_), "r"(0u) : "memory");
}
#endif  // HAS_TCG

// ---------------- weight preprocessing (coalesced 16B writes) ----------------
__global__ __launch_bounds__(256) void prep_gated(const float* __restrict__ Wf,
                                                  const float* __restrict__ Wg) {
    uint32_t idx = blockIdx.x * 256u + threadIdx.x;
    int n7 = idx & 127, kq = (idx >> 7) & 7, c = (idx >> 10) & 7;
    int nb = (idx >> 13) & 1, i = idx >> 14;
    char* base = g_gB + (((size_t)(i * 2 + nb) * 8 + c) * 4) * TILE_B;
    uint32_t off = swz128((uint32_t)n7 * 128u + (uint32_t)kq * 16u);
    unsigned short fh[8], fl[8], gh[8], gl[8];
    #pragma unroll
    for (int e = 0; e < 8; ++e) {
        int k = c * 64 + kq * 8 + e;
        size_t o = (size_t)i * 131072 + (size_t)k * 256 + nb * 128 + n7;
        __nv_bfloat16 h, l;
        split2(Wf[o], h, l); fh[e] = __bfloat16_as_ushort(h); fl[e] = __bfloat16_as_ushort(l);
        split2(Wg[o], h, l); gh[e] = __bfloat16_as_ushort(h); gl[e] = __bfloat16_as_ushort(l);
    }
    *(uint4*)(base + 0 * TILE_B + off) = pack8(fh);
    *(uint4*)(base + 1 * TILE_B + off) = pack8(fl);
    *(uint4*)(base + 2 * TILE_B + off) = pack8(gh);
    *(uint4*)(base + 3 * TILE_B + off) = pack8(gl);
}
__global__ __launch_bounds__(256) void prep_res(const float* __restrict__ Wr,
                                                const float* __restrict__ Ws) {
    uint32_t idx = blockIdx.x * 256u + threadIdx.x;
    int n7 = idx & 127, kq = (idx >> 7) & 7, c = (idx >> 10) & 3;
    int nb = (idx >> 12) & 1, i = idx >> 13;
    char* base = g_rB + (((size_t)(i * 2 + nb) * 4 + c) * 4) * TILE_B;
    uint32_t off = swz128((uint32_t)n7 * 128u + (uint32_t)kq * 16u);
    unsigned short rh[8], rl[8], sh[8], sl[8];
    #pragma unroll
    for (int e = 0; e < 8; ++e) {
        int k = c * 64 + kq * 8 + e;
        size_t o = (size_t)i * 65536 + (size_t)k * 256 + nb * 128 + n7;
        __nv_bfloat16 h, l;
        split2(Wr[o], h, l); rh[e] = __bfloat16_as_ushort(h); rl[e] = __bfloat16_as_ushort(l);
        split2(Ws[o], h, l); sh[e] = __bfloat16_as_ushort(h); sl[e] = __bfloat16_as_ushort(l);
    }
    *(uint4*)(base + 0 * TILE_B + off) = pack8(rh);
    *(uint4*)(base + 1 * TILE_B + off) = pack8(rl);
    *(uint4*)(base + 2 * TILE_B + off) = pack8(sh);
    *(uint4*)(base + 3 * TILE_B + off) = pack8(sl);
}
__global__ __launch_bounds__(256) void prep_conv(const float* __restrict__ Wc) {
    uint32_t idx = blockIdx.x * 256u + threadIdx.x;
    int n7 = idx & 127, kq = (idx >> 7) & 7, c = (idx >> 10) & 1, nb = (idx >> 11) & 1;
    char* base = g_cB + (((size_t)nb * 2 + c) * 2) * TILE_B;
    uint32_t off = swz128((uint32_t)n7 * 128u + (uint32_t)kq * 16u);
    unsigned short hv[8], lv[8];
    #pragma unroll
    for (int e = 0; e < 8; ++e) {
        int k = c * 64 + kq * 8 + e;
        size_t o = (size_t)k * 256 + nb * 128 + n7;
        __nv_bfloat16 h, l;
        split2(Wc[o], h, l); hv[e] = __bfloat16_as_ushort(h); lv[e] = __bfloat16_as_ushort(l);
    }
    *(uint4*)(base + 0 * TILE_B + off) = pack8(hv);
    *(uint4*)(base + 1 * TILE_B + off) = pack8(lv);
}

// ---------------- A-tile fills (128-row tile, SW128) ----------------
__device__ __forceinline__ void fill_A_f32(char* Ah, char* Al, const float* Asrc,
                                           int b, int srow, int fr, int cg,
                                           int c, int shift_chunks, int dil) {
    const int tsh  = (c < shift_chunks) ? dil : 0;
    const int kcol = (c < shift_chunks) ? c * 64 : (c - shift_chunks) * 64;
    const int t = srow - tsh;
    const bool valid = srow >= tsh;
    const float* src = Asrc + ((size_t)(b * T_ + t)) * 64 + kcol + cg;
    #pragma unroll
    for (int j = 0; j < 8; ++j) {
        float4 v = valid ? *(const float4*)(src + j * 4) : make_float4(0.f, 0.f, 0.f, 0.f);
        uint32_t off = swz128((uint32_t)fr * 128u + (uint32_t)(cg + j * 4) * 2u);
        __nv_bfloat16 h0, l0, h1, l1, h2, l2, h3, l3;
        split2(v.x, h0, l0); split2(v.y, h1, l1);
        split2(v.z, h2, l2); split2(v.w, h3, l3);
        uint2 hh, ll;
        hh.x = (uint32_t)__bfloat16_as_ushort(h0) | ((uint32_t)__bfloat16_as_ushort(h1) << 16);
        hh.y = (uint32_t)__bfloat16_as_ushort(h2) | ((uint32_t)__bfloat16_as_ushort(h3) << 16);
        ll.x = (uint32_t)__bfloat16_as_ushort(l0) | ((uint32_t)__bfloat16_as_ushort(l1) << 16);
        ll.y = (uint32_t)__bfloat16_as_ushort(l2) | ((uint32_t)__bfloat16_as_ushort(l3) << 16);
        *(uint2*)(Ah + off) = hh;
        *(uint2*)(Al + off) = ll;
    }
}
__device__ __forceinline__ void fill_A_bf16(char* Ah, char* Al,
                                            const __nv_bfloat16* __restrict__ sh,
                                            const __nv_bfloat16* __restrict__ sl,
                                            int b, int srow, int fr, int cg,
                                            int c, int shift_chunks, int dil) {
    const int tsh  = (c < shift_chunks) ? dil : 0;
    const int kcol = (c < shift_chunks) ? c * 64 : (c - shift_chunks) * 64;
    const int t = srow - tsh;
    const bool valid = srow >= tsh;
    const size_t eoff = ((size_t)(b * T_ + t)) * F_ + kcol + cg;
    const uint4* ph = (const uint4*)(sh + eoff);
    const uint4* pl = (const uint4*)(sl + eoff);
    #pragma unroll
    for (int j = 0; j < 4; ++j) {
        uint4 vh = valid ? ph[j] : make_uint4(0, 0, 0, 0);
        uint4 vl = valid ? pl[j] : make_uint4(0, 0, 0, 0);
        uint32_t off = swz128((uint32_t)fr * 128u + (uint32_t)(cg + j * 8) * 2u);
        *(uint4*)(Ah + off) = vh;
        *(uint4*)(Al + off) = vl;
    }
}

__device__ __forceinline__ void store_hl8(__nv_bfloat16* hd, __nv_bfloat16* ld,
                                          size_t eoff, const float* v) {
    unsigned short hu[8], lu[8];
    #pragma unroll
    for (int e = 0; e < 8; ++e) {
        __nv_bfloat16 h, l; split2(v[e], h, l);
        hu[e] = __bfloat16_as_ushort(h); lu[e] = __bfloat16_as_ushort(l);
    }
    *(uint4*)(hd + eoff) = pack8(hu);
    *(uint4*)(ld + eoff) = pack8(lu);
}
__device__ __forceinline__ void load_hl8(const __nv_bfloat16* hd, const __nv_bfloat16* ld,
                                         size_t eoff, float* v) {
    uint4 hh = *(const uint4*)(hd + eoff);
    uint4 ll = *(const uint4*)(ld + eoff);
    const uint32_t* hp = &hh.x;
    const uint32_t* lp = &ll.x;
    #pragma unroll
    for (int e = 0; e < 4; ++e) {
        __nv_bfloat162 h2 = *(__nv_bfloat162*)&hp[e];
        __nv_bfloat162 l2 = *(__nv_bfloat162*)&lp[e];
        float2 fh = __bfloat1622float2(h2), fl = __bfloat1622float2(l2);
        v[2 * e] = fh.x + fl.x;
        v[2 * e + 1] = fh.y + fl.y;
    }
}
__device__ __forceinline__ float2 dec2(const char* hp, const char* lp, uint32_t off) {
    __nv_bfloat162 h = *(const __nv_bfloat162*)(hp + off);
    __nv_bfloat162 l = *(const __nv_bfloat162*)(lp + off);
    float2 fh = __bfloat1622float2(h), fl = __bfloat1622float2(l);
    return make_float2(fh.x + fl.x, fh.y + fl.y);
}

// ---------------- GEMM layer: M=128/CTA, single-buffered, 2 CTAs/SM ----------------
__global__ __launch_bounds__(256, 2) void mma_layer(
    const float* __restrict__ Af32,
    const __nv_bfloat16* __restrict__ Abh, const __nv_bfloat16* __restrict__ Abl,
    const char* __restrict__ Bbase,
    const float* __restrict__ br, const float* __restrict__ bs,
    int n_chunks, int n_mats, int shift_chunks, int dil, int mode, int first)
{
    extern __shared__ char smem[];
    const int tid = threadIdx.x;
    const int m0 = blockIdx.x * 128;
    const int n0 = blockIdx.y * 128;
    const int b  = m0 / T_;
    const int t0 = m0 % T_;
    const int n_tiles = n_mats * 2;
    const uint32_t bbytes = (uint32_t)n_tiles * TILE_B;
    const int fr = tid >> 1;
    const int cg = (tid & 1) * 32;

#if HAS_TCG
    const uint32_t sbase = smem_u32(smem);
    const int wid = tid >> 5;
    const uint32_t mC  = sbase;
    const uint32_t bb  = sbase + 8;
    const uint32_t tptr = sbase + 16;
    const uint32_t abase = sbase + 1024;
    const uint32_t bsm   = abase + 32768;
    char* Ah = smem + 1024;
    char* Al = Ah + TILE_B;

    if (tid == 0) { MBARRIER_INIT(mC, 1); MBARRIER_INIT(bb, 1); }
    if (wid == 0) {
        TCGEN05_ALLOC(tptr, 256);
        TCGEN05_RELINQ();
    }
    __syncthreads();
    uint32_t tmem;
    asm volatile("ld.shared.b32 %0, [%1];" : "=r"(tmem) : "r"(tptr));

    if (tid == 0) {
        MBARRIER_EXPECT_TX(bb, bbytes);
        CP_BULK_G2S(bsm, Bbase + ((size_t)(blockIdx.y * n_chunks) * n_tiles) * TILE_B,
                    bbytes, bb);
    }

    for (int c = 0; c < n_chunks; ++c) {
        if (c >= 1) {
            MBARRIER_WAIT_PARITY(mC, (c - 1) & 1);
            if (tid == 0) {
                MBARRIER_EXPECT_TX(bb, bbytes);
                CP_BULK_G2S(bsm,
                            Bbase + ((size_t)(blockIdx.y * n_chunks + c) * n_tiles) * TILE_B,
                            bbytes, bb);
            }
        }
        if (mode == 0) fill_A_f32(Ah, Al, Af32, b, t0 + fr, fr, cg, c, shift_chunks, dil);
        else           fill_A_bf16(Ah, Al, Abh, Abl, b, t0 + fr, fr, cg, c, shift_chunks, dil);
        FENCE_PROXY_ASYNC();
        __syncthreads();

        if (wid == 0) {
            MBARRIER_WAIT_PARITY(bb, c & 1);
            if (elect_one_pred()) {
                const uint64_t ah = make_desc(abase);
                const uint64_t al = make_desc(abase + TILE_B);
                for (int mat = 0; mat < n_mats; ++mat) {
                    const uint64_t bh = make_desc(bsm + (uint32_t)(mat * 2) * TILE_B);
                    const uint64_t bl = make_desc(bsm + (uint32_t)(mat * 2 + 1) * TILE_B);
                    const uint32_t dD = tmem + mat * 128;
                    #pragma unroll
                    for (int ks = 0; ks < 4; ++ks)
                        mma_f16(dD, ah + ks * 2, bh + ks * 2, !(c == 0 && ks == 0));
                    #pragma unroll
                    for (int ks = 0; ks < 4; ++ks)
                        mma_f16(dD, ah + ks * 2, bl + ks * 2, 1u);
                    #pragma unroll
                    for (int ks = 0; ks < 4; ++ks)
                        mma_f16(dD, al + ks * 2, bh + ks * 2, 1u);
                }
                TCGEN05_COMMIT(mC);
            }
        }
    }

    MBARRIER_WAIT_PARITY(mC, (n_chunks - 1) & 1);
    TCGEN05_FENCE_AFTER();

    {
        const int lane = tid & 31;
        const int m = m0 + (wid & 3) * 32 + lane;
        const int half = wid >> 2;
        #pragma unroll
        for (int q = 0; q < 4; ++q) {
            const int colc = half * 64 + q * 16;
            uint32_t rf[16], rg[16];
            TCGEN05_LD_X16(rf, tmem + colc);
            if (n_mats == 2) TCGEN05_LD_X16(rg, tmem + 128 + colc);
            TCGEN05_WAIT_LD();
            const int nc = n0 + colc;
            const size_t rbase = (size_t)m * F_ + nc;
            if (mode == 1) {
                #pragma unroll
                for (int jq = 0; jq < 2; ++jq) {
                    float vv[8];
                    #pragma unroll
                    for (int e = 0; e < 8; ++e)
                        vv[e] = gate_fast(__uint_as_float(rf[jq * 8 + e]),
                                          __uint_as_float(rg[jq * 8 + e]));
                    store_hl8(g_zh, g_zl, rbase + jq * 8, vv);
                }
            } else if (mode == 0) {
                #pragma unroll
                for (int jq = 0; jq < 2; ++jq) {
                    float vv[8];
                    #pragma unroll
                    for (int e = 0; e < 8; ++e) vv[e] = __uint_as_float(rf[jq * 8 + e]);
                    store_hl8(g_outh, g_outl, rbase + jq * 8, vv);
                }
            } else {
                #pragma unroll
                for (int jq = 0; jq < 2; ++jq) {
                    float vv[8];
                    load_hl8(g_outh, g_outl, rbase + jq * 8, vv);
                    #pragma unroll
                    for (int e = 0; e < 8; ++e) {
                        const size_t off = rbase + jq * 8 + e;
                        const int n = nc + jq * 8 + e;
                        vv[e] += __uint_as_float(rf[jq * 8 + e]) + __ldg(&br[n]);
                        const float sp = first ? 0.0f : g_skip[off];
                        g_skip[off] = sp + __uint_as_float(rg[jq * 8 + e]) + __ldg(&bs[n]);
                    }
                    store_hl8(g_outh, g_outl, rbase + jq * 8, vv);
                }
            }
        }
    }
    __syncthreads();
    if (tid == 0) { MBARRIER_INVAL(mC); MBARRIER_INVAL(bb); }
    if (wid == 0) TCGEN05_DEALLOC(tmem, 256);
#else
    // ---- generic-arch fallback (compile-only; runtime uses sm_103a cubin) ----
    char* Ah = smem;
    char* Al = smem + TILE_B;
    char* Bt = smem + 2 * TILE_B;
    const int ty = tid >> 4, tx = tid & 15;

    for (int mat = 0; mat < n_mats; ++mat) {
        float acc[8][8];
        #pragma unroll
        for (int i = 0; i < 8; ++i)
            #pragma unroll
            for (int j = 0; j < 8; ++j) acc[i][j] = 0.0f;
        for (int c = 0; c < n_chunks; ++c) {
            __syncthreads();
            if (mode == 0) fill_A_f32(Ah, Al, Af32, b, t0 + fr, fr, cg, c, shift_chunks, dil);
            else           fill_A_bf16(Ah, Al, Abh, Abl, b, t0 + fr, fr, cg, c, shift_chunks, dil);
            {
                const char* cb = Bbase + ((size_t)(blockIdx.y * n_chunks + c) * n_tiles) * TILE_B;
                const uint4* srcH = (const uint4*)(cb + (size_t)(mat * 2) * TILE_B);
                const uint4* srcL = (const uint4*)(cb + (size_t)(mat * 2 + 1) * TILE_B);
                uint4* dst = (uint4*)Bt;
                for (int j = tid; j < 1024; j += 256) { dst[j] = srcH[j]; dst[j + 1024] = srcL[j]; }
            }
            __syncthreads();
            #pragma unroll 4
            for (int k2 = 0; k2 < 32; ++k2) {
                float2 a2[8], b2[8];
                #pragma unroll
                for (int i = 0; i < 8; ++i)
                    a2[i] = dec2(Ah, Al, swz128((uint32_t)(ty * 8 + i) * 128u + k2 * 4u));
                #pragma unroll
                for (int j = 0; j < 8; ++j)
                    b2[j] = dec2(Bt, Bt + TILE_B, swz128((uint32_t)(tx * 8 + j) * 128u + k2 * 4u));
                #pragma unroll
                for (int i = 0; i < 8; ++i)
                    #pragma unroll
                    for (int j = 0; j < 8; ++j)
                        acc[i][j] += a2[i].x * b2[j].x + a2[i].y * b2[j].y;
            }
        }
        #pragma unroll
        for (int i = 0; i < 8; ++i) {
            const int m = m0 + ty * 8 + i;
            #pragma unroll
            for (int j = 0; j < 8; ++j) {
                const int n = n0 + tx * 8 + j;
                const size_t off = (size_t)m * F_ + n;
                if (mode == 0) {
                    __nv_bfloat16 h, l; split2(acc[i][j], h, l);
                    g_outh[off] = h; g_outl[off] = l;
                } else if (mode == 1) {
                    if (mat == 0) g_tmp[off] = acc[i][j];
                    else {
                        float z = gate_fast(g_tmp[off], acc[i][j]);
                        __nv_bfloat16 h, l; split2(z, h, l);
                        g_zh[off] = h; g_zl[off] = l;
                    }
                } else {
                    if (mat == 0) {
                        float v = __bfloat162float(g_outh[off]) +
                                  __bfloat162float(g_outl[off]) + acc[i][j] + br[n];
                        __nv_bfloat16 h, l; split2(v, h, l);
                        g_outh[off] = h; g_outl[off] = l;
                    } else {
                        const float sp = first ? 0.0f : g_skip[off];
                        g_skip[off] = sp + acc[i][j] + bs[n];
                    }
                }
            }
        }
    }
#endif
}

// ---------------- head: 32 rows/block, 8 outputs/thread ----------------
__global__ __launch_bounds__(256) void head_kernel(
    const float* __restrict__ Wd1, const float* __restrict__ bd1,
    const float* __restrict__ Wd2, const float* __restrict__ bd2,
    float* __restrict__ y) {
    __shared__ float hs[32][260];
    __shared__ float h2s[32][68];
    const int m0 = blockIdx.x * 32;
    const int r  = threadIdx.x >> 3;
    const int cg = (threadIdx.x & 7) * 8;

    for (int idx = threadIdx.x; idx < 32 * 64; idx += 256) {
        const int row = idx >> 6;
        const int c4  = (idx & 63) * 4;
        float4 v = *(const float4*)&g_skip[(size_t)(m0 + row) * F_ + c4];
        hs[row][c4 + 0] = seluf_(v.x); hs[row][c4 + 1] = seluf_(v.y);
        hs[row][c4 + 2] = seluf_(v.z); hs[row][c4 + 3] = seluf_(v.w);
    }
    __syncthreads();

    float acc[8];
    #pragma unroll
    for (int e = 0; e < 8; ++e) acc[e] = bd1[cg + e];
    #pragma unroll 4
    for (int k = 0; k < 256; ++k) {
        const float h = hs[r][k];
        float4 w0 = __ldg((const float4*)&Wd1[(size_t)k * 64 + cg]);
        float4 w1 = __ldg((const float4*)&Wd1[(size_t)k * 64 + cg + 4]);
        acc[0] += h * w0.x; acc[1] += h * w0.y; acc[2] += h * w0.z; acc[3] += h * w0.w;
        acc[4] += h * w1.x; acc[5] += h * w1.y; acc[6] += h * w1.z; acc[7] += h * w1.w;
    }
    #pragma unroll
    for (int e = 0; e < 8; ++e) h2s[r][cg + e] = seluf_(acc[e]);
    __syncthreads();

    float a2[8];
    #pragma unroll
    for (int e = 0; e < 8; ++e) a2[e] = bd2[cg + e];
    #pragma unroll 4
    for (int k = 0; k < 64; ++k) {
        const float h = h2s[r][k];
        float4 w0 = __ldg((const float4*)&Wd2[(size_t)k * 64 + cg]);
        float4 w1 = __ldg((const float4*)&Wd2[(size_t)k * 64 + cg + 4]);
        a2[0] += h * w0.x; a2[1] += h * w0.y; a2[2] += h * w0.z; a2[3] += h * w0.w;
        a2[4] += h * w1.x; a2[5] += h * w1.y; a2[6] += h * w1.z; a2[7] += h * w1.w;
    }
    float* yp = &y[(size_t)(m0 + r) * 64 + cg];
    *(float4*)yp       = make_float4(a2[0], a2[1], a2[2], a2[3]);
    *(float4*)(yp + 4) = make_float4(a2[4], a2[5], a2[6], a2[7]);
}

// ---------------------------------------------------------------------------
extern "C" void kernel_launch(void* const* d_in, const int* in_sizes, int n_in,
                              void* d_out, int out_size) {
    const float* x   = (const float*)d_in[0];
    const float* Wc  = (const float*)d_in[1];
    const float* Wf  = (const float*)d_in[2];
    const float* Wg  = (const float*)d_in[3];
    const float* Wr  = (const float*)d_in[4];
    const float* br  = (const float*)d_in[5];
    const float* Ws  = (const float*)d_in[6];
    const float* bs  = (const float*)d_in[7];
    const float* Wd1 = (const float*)d_in[8];
    const float* bd1 = (const float*)d_in[9];
    const float* Wd2 = (const float*)d_in[10];
    const float* bd2 = (const float*)d_in[11];
    float* y = (float*)d_out;

    cudaFuncSetAttribute(mma_layer, cudaFuncAttributeMaxDynamicSharedMemorySize, SMEM_BYTES);
    cudaFuncSetAttribute(mma_layer, cudaFuncAttributePreferredSharedMemoryCarveout, 100);

    char* gB; cudaGetSymbolAddress((void**)&gB, g_gB);
    char* rB; cudaGetSymbolAddress((void**)&rB, g_rB);
    char* cB; cudaGetSymbolAddress((void**)&cB, g_cB);
    __nv_bfloat16 *oh, *ol, *zh, *zl;
    cudaGetSymbolAddress((void**)&oh, g_outh);
    cudaGetSymbolAddress((void**)&ol, g_outl);
    cudaGetSymbolAddress((void**)&zh, g_zh);
    cudaGetSymbolAddress((void**)&zl, g_zl);

    prep_gated<<<512, 256>>>(Wf, Wg);   // launch 0
    prep_res  <<<256, 256>>>(Wr, Ws);   // launch 1
    prep_conv <<<16,  256>>>(Wc);       // launch 2

    dim3 grid(M_ / 128, 2), blk(256);
    // launch 3
    mma_layer<<<grid, blk, SMEM_BYTES>>>(x, nullptr, nullptr, cB, nullptr, nullptr,
                                         2, 1, 1, 1, 0, 0);
    // launch 4: idempotent dummy so ncu (-s 5) samples gated0 at launch index 5
    prep_conv <<<16,  256>>>(Wc);
    for (int i = 0; i < NL; ++i) {
        const int d = 2 << i;
        mma_layer<<<grid, blk, SMEM_BYTES>>>(
            nullptr, oh, ol, gB + (size_t)i * 2 * 8 * 4 * TILE_B, nullptr, nullptr,
            8, 2, 4, d, 1, 0);
        mma_layer<<<grid, blk, SMEM_BYTES>>>(
            nullptr, zh, zl, rB + (size_t)i * 2 * 4 * 4 * TILE_B,
            br + (size_t)i * F_, bs + (size_t)i * F_,
            4, 2, 0, 0, 2, i == 0);
    }
    head_kernel<<<M_ / 32, 256>>>(Wd1, bd1, Wd2, bd2, y);
}